// round 5
// baseline (speedup 1.0000x reference)
#include <cuda_runtime.h>
#include <math.h>

typedef unsigned long long ull;

#define Bsz 32
#define Ssz 128
#define Tsz 128
#define Hsz 1024
#define G3H 3072
#define Esz 512
#define Vsz 32000
#define NBLK 250

// ---------------- static scratch ----------------
__device__ float g_gi[(size_t)Ssz * Bsz * G3H];   // bulk input-gates
__device__ float g_ys0[(size_t)Ssz * Bsz * Hsz];  // encoder layer0 outputs
__device__ float g_px[(size_t)4 * Bsz * G3H];     // split-K partials (x-part)
__device__ float g_ph[(size_t)4 * Bsz * G3H];     // split-K partials (h-part)
__device__ float g_h1[Bsz * Hsz];
__device__ float g_h2[Bsz * Hsz];
__device__ int g_tok[Bsz];
__device__ ull g_amax[Bsz];
__device__ unsigned g_bar_count = 0;
__device__ volatile unsigned g_bar_gen = 0;

// ---------------- small helpers ----------------
__device__ __forceinline__ ull ffma2(ull a, ull b, ull c) {
    ull d;
    asm("fma.rn.f32x2 %0, %1, %2, %3;" : "=l"(d) : "l"(a), "l"(b), "l"(c));
    return d;
}
__device__ __forceinline__ ull dup2(float x) {
    ull d;
    asm("mov.b64 %0, {%1, %1};" : "=l"(d) : "f"(x));
    return d;
}
__device__ __forceinline__ float2 up2(ull v) {
    float2 f;
    asm("mov.b64 {%0, %1}, %2;" : "=f"(f.x), "=f"(f.y) : "l"(v));
    return f;
}
__device__ __forceinline__ ull packkey(float v, int c) {
    unsigned b = __float_as_uint(v);
    b = (b & 0x80000000u) ? ~b : (b | 0x80000000u);
    return ((ull)b << 32) | (ull)(0xFFFFFFFFu - (unsigned)c);
}

// grid barrier: sense-reversing, generation monotonic across graph replays
__device__ __forceinline__ void gbar() {
    __syncthreads();
    __threadfence();   // release: my global writes visible
    if (threadIdx.x == 0) {
        unsigned gen = g_bar_gen;
        if (atomicAdd(&g_bar_count, 1u) == gridDim.x - 1u) {
            g_bar_count = 0u;
            __threadfence();
            g_bar_gen = gen + 1u;
        } else {
            while (g_bar_gen == gen) __nanosleep(32);
        }
    }
    __syncthreads();
    __threadfence();   // acquire: invalidate L1 so we see peers' writes
}

// ---------------- tile GEMM: 32 rows x 64 cols, 128 threads, FFMA2 ----------------
__device__ __forceinline__ void lda64(ull (*As2)[66], const float* __restrict__ A,
                                      const int* toks, int lda, int kb, int tid) {
#pragma unroll
    for (int r = 0; r < 4; r++) {
        int f4 = tid + r * 128, b = f4 >> 4, kq = f4 & 15;
        size_t ro = toks ? (size_t)toks[b] * lda : (size_t)b * lda;
        float4 v = *(const float4*)(A + ro + kb + kq * 4);
        As2[b][kq * 4 + 0] = dup2(v.x); As2[b][kq * 4 + 1] = dup2(v.y);
        As2[b][kq * 4 + 2] = dup2(v.z); As2[b][kq * 4 + 3] = dup2(v.w);
    }
}
__device__ __forceinline__ void ldw64(float (*Wsf)[68], const float* __restrict__ W,
                                      int ldw, int cbase, int kb, int tid) {
#pragma unroll
    for (int r = 0; r < 8; r++) {
        int f4 = tid + r * 128, c = f4 >> 4, kq = f4 & 15;
        float4 v = *(const float4*)(W + (size_t)(cbase + c) * ldw + kb + kq * 4);
        Wsf[kq * 4 + 0][c] = v.x; Wsf[kq * 4 + 1][c] = v.y;
        Wsf[kq * 4 + 2][c] = v.z; Wsf[kq * 4 + 3][c] = v.w;
    }
}
__device__ __forceinline__ void mm64(const ull (*As2)[66], const float (*Wsf)[68],
                                     ull acc[4][2], int bg, int cg) {
#pragma unroll
    for (int kk = 0; kk < 64; kk++) {
        ull w0 = *(const ull*)&Wsf[kk][2 * cg];
        ull w1 = *(const ull*)&Wsf[kk][2 * cg + 32];
        ull a0 = As2[bg][kk], a1 = As2[bg + 8][kk];
        ull a2 = As2[bg + 16][kk], a3 = As2[bg + 24][kk];
        acc[0][0] = ffma2(a0, w0, acc[0][0]); acc[0][1] = ffma2(a0, w1, acc[0][1]);
        acc[1][0] = ffma2(a1, w0, acc[1][0]); acc[1][1] = ffma2(a1, w1, acc[1][1]);
        acc[2][0] = ffma2(a2, w0, acc[2][0]); acc[2][1] = ffma2(a2, w1, acc[2][1]);
        acc[3][0] = ffma2(a3, w0, acc[3][0]); acc[3][1] = ffma2(a3, w1, acc[3][1]);
    }
}
__device__ __forceinline__ void gemm_acc(ull (*As2)[66], float (*Wsf)[68],
                                         const float* A, const int* toks, int lda,
                                         const float* W, int ldw,
                                         int kbase, int nchunk, int cbase,
                                         ull acc[4][2]) {
    int tid = threadIdx.x, bg = tid >> 4, cg = tid & 15;
    for (int c = 0; c < nchunk; c++) {
        __syncthreads();
        lda64(As2, A, toks, lda, kbase + c * 64, tid);
        ldw64(Wsf, W, ldw, cbase, kbase + c * 64, tid);
        __syncthreads();
        mm64(As2, Wsf, acc, bg, cg);
    }
}
__device__ __forceinline__ void store_partial(ull acc[4][2], float* outp, int cbase, int tid) {
    int bg = tid >> 4, cg = tid & 15;
#pragma unroll
    for (int i = 0; i < 4; i++) {
        float2 p0 = up2(acc[i][0]), p1 = up2(acc[i][1]);
        float* o = outp + (size_t)(bg + 8 * i) * G3H + cbase;
        *(float2*)(o + 2 * cg) = p0;
        *(float2*)(o + 2 * cg + 32) = p1;
    }
}

// ---------------- GRU gate math ----------------
__device__ __forceinline__ void gates_idx(int idx, const float* gi_pre,
                                          int nx, const float* bih,
                                          int nh, const float* bhh,
                                          float* h, float* ys) {
    int b = idx >> 10, j = idx & 1023;
    float ir, iz, in_;
    if (gi_pre) {
        const float* g = gi_pre + (size_t)b * G3H;
        ir = g[j]; iz = g[Hsz + j]; in_ = g[2 * Hsz + j];
    } else {
        ir = bih[j]; iz = bih[Hsz + j]; in_ = bih[2 * Hsz + j];
        for (int s = 0; s < nx; s++) {
            const float* p = g_px + (size_t)s * Bsz * G3H + (size_t)b * G3H;
            ir += p[j]; iz += p[Hsz + j]; in_ += p[2 * Hsz + j];
        }
    }
    float hr = bhh[j], hz = bhh[Hsz + j], hn = bhh[2 * Hsz + j];
    for (int s = 0; s < nh; s++) {
        const float* p = g_ph + (size_t)s * Bsz * G3H + (size_t)b * G3H;
        hr += p[j]; hz += p[Hsz + j]; hn += p[2 * Hsz + j];
    }
    float r = 1.f / (1.f + expf(-(ir + hr)));
    float z = 1.f / (1.f + expf(-(iz + hz)));
    float n = tanhf(in_ + r * hn);
    float hv = h[idx];
    float hnew = (1.f - z) * n + z * hv;
    h[idx] = hnew;
    if (ys) ys[idx] = hnew;
}

// ---------------- kernels ----------------
__global__ void k_init(const int* __restrict__ trg) {
    int i = blockIdx.x * blockDim.x + threadIdx.x;
    if (i < Bsz * Hsz) { g_h1[i] = 0.f; g_h2[i] = 0.f; }
    if (i < Bsz) { g_tok[i] = trg[i * Tsz]; g_amax[i] = 0ull; }
}

__global__ void k_zero0(float* __restrict__ out) {
    int i = blockIdx.x * blockDim.x + threadIdx.x;
    if (i < Bsz * Vsz) {
        int b = i / Vsz, v = i - b * Vsz;
        out[(size_t)b * ((size_t)Tsz * Vsz) + v] = 0.f;
    }
}

// bulk input-gate GEMM: g_gi[(t*32+b)][c] = x . W[c] + bias[c]
__global__ void __launch_bounds__(128, 2) k_big(
    const float* __restrict__ emb, const int* __restrict__ src,
    const float* __restrict__ W, const float* __restrict__ bias,
    int K, int gather)
{
    __shared__ ull As2[32][66];
    __shared__ float Wsf[64][68];
    __shared__ int s_tok[32];
    int tid = threadIdx.x, tblk = blockIdx.y, cbase = blockIdx.x * 64;
    const float* A; int lda; const int* tp = nullptr;
    if (gather) {
        if (tid < 32) s_tok[tid] = src[tid * Ssz + tblk];
        tp = s_tok; A = emb; lda = Esz;
    } else {
        A = g_ys0 + (size_t)tblk * Bsz * Hsz; lda = Hsz;
    }
    __syncthreads();
    ull acc[4][2] = {};
    gemm_acc(As2, Wsf, A, tp, lda, W, K, 0, K / 64, cbase, acc);
    int bg = tid >> 4, cg = tid & 15;
#pragma unroll
    for (int i = 0; i < 4; i++) {
        float2 p0 = up2(acc[i][0]), p1 = up2(acc[i][1]);
        int c0 = cbase + 2 * cg;
        float* o = g_gi + (size_t)(tblk * Bsz + bg + 8 * i) * G3H;
        *(float2*)(o + c0) = make_float2(p0.x + bias[c0], p0.y + bias[c0 + 1]);
        *(float2*)(o + c0 + 32) = make_float2(p1.x + bias[c0 + 32], p1.y + bias[c0 + 33]);
    }
}

// persistent encoder layer: 128 recurrent steps with grid barriers
__global__ void __launch_bounds__(128, 2) k_enc(
    const float* __restrict__ U, const float* __restrict__ bhh, int layer)
{
    __shared__ ull As2[32][66];
    __shared__ float Wsf[64][68];
    int tid = threadIdx.x, bid = blockIdx.x;
    float* h = layer ? g_h2 : g_h1;
    for (int t = 0; t < Ssz; t++) {
        for (int task = bid; task < 192; task += NBLK) {
            int cb = task >> 2, s = task & 3;
            ull acc[4][2] = {};
            gemm_acc(As2, Wsf, h, nullptr, Hsz, U, Hsz, s * 256, 4, cb * 64, acc);
            store_partial(acc, g_ph + (size_t)s * Bsz * G3H, cb * 64, tid);
        }
        gbar();
        const float* gi = g_gi + (size_t)t * Bsz * G3H;
        float* ys = layer ? nullptr : (g_ys0 + (size_t)t * Bsz * Hsz);
        for (int idx = bid * 128 + tid; idx < Bsz * Hsz; idx += NBLK * 128)
            gates_idx(idx, gi, 0, nullptr, 4, bhh, h, ys);
        gbar();
    }
}

// persistent decoder: 127 greedy steps, 5 phases per step
__global__ void __launch_bounds__(128, 2) k_dec(
    const float* __restrict__ demb,
    const float* __restrict__ dW0, const float* __restrict__ dU0,
    const float* __restrict__ dbi0, const float* __restrict__ dbh0,
    const float* __restrict__ dW1, const float* __restrict__ dU1,
    const float* __restrict__ dbi1, const float* __restrict__ dbh1,
    const float* __restrict__ fcW, const float* __restrict__ fcb,
    float* __restrict__ out)
{
    __shared__ ull As2[32][66];
    __shared__ float Wsf[64][68];
    __shared__ int s_tok[32];
    __shared__ ull sk[32];
    int tid = threadIdx.x, bid = blockIdx.x;
    for (int step = 0; step < Tsz - 1; step++) {
        if (tid < 32)
            s_tok[tid] = (step == 0)
                ? g_tok[tid]
                : (int)(0xFFFFFFFFu - (unsigned)(g_amax[tid] & 0xFFFFFFFFull));
        __syncthreads();
        // P1: layer0 gi (emb gather, K=512) + gh (h1, K=1024) partials
        for (int task = bid; task < 288; task += NBLK) {
            ull acc[4][2] = {};
            if (task < 96) {
                int cb = task >> 1, s = task & 1;
                gemm_acc(As2, Wsf, demb, s_tok, Esz, dW0, Esz, s * 256, 4, cb * 64, acc);
                store_partial(acc, g_px + (size_t)s * Bsz * G3H, cb * 64, tid);
            } else {
                int t2 = task - 96, cb = t2 >> 2, s = t2 & 3;
                gemm_acc(As2, Wsf, g_h1, nullptr, Hsz, dU0, Hsz, s * 256, 4, cb * 64, acc);
                store_partial(acc, g_ph + (size_t)s * Bsz * G3H, cb * 64, tid);
            }
        }
        gbar();
        // P2: gates -> h1 ; reset argmax accumulator
        for (int idx = bid * 128 + tid; idx < Bsz * Hsz; idx += NBLK * 128)
            gates_idx(idx, nullptr, 2, dbi0, 4, dbh0, g_h1, nullptr);
        if (bid == 0 && tid < 32) g_amax[tid] = 0ull;
        gbar();
        // P3: layer1 gi (h1new) + gh (h2) partials
        for (int task = bid; task < 384; task += NBLK) {
            ull acc[4][2] = {};
            if (task < 192) {
                int cb = task >> 2, s = task & 3;
                gemm_acc(As2, Wsf, g_h1, nullptr, Hsz, dW1, Hsz, s * 256, 4, cb * 64, acc);
                store_partial(acc, g_px + (size_t)s * Bsz * G3H, cb * 64, tid);
            } else {
                int t2 = task - 192, cb = t2 >> 2, s = t2 & 3;
                gemm_acc(As2, Wsf, g_h2, nullptr, Hsz, dU1, Hsz, s * 256, 4, cb * 64, acc);
                store_partial(acc, g_ph + (size_t)s * Bsz * G3H, cb * 64, tid);
            }
        }
        gbar();
        // P4: gates -> h2
        for (int idx = bid * 128 + tid; idx < Bsz * Hsz; idx += NBLK * 128)
            gates_idx(idx, nullptr, 4, dbi1, 4, dbh1, g_h2, nullptr);
        gbar();
        // P5: FC + logits out + deterministic argmax
        for (int task = bid; task < 500; task += NBLK) {
            int cbase = task * 64;
            if (tid < 32) sk[tid] = 0ull;
            ull acc[4][2] = {};
            gemm_acc(As2, Wsf, g_h2, nullptr, Hsz, fcW, Hsz, 0, 16, cbase, acc);
            int bg = tid >> 4, cg = tid & 15;
#pragma unroll
            for (int i = 0; i < 4; i++) {
                int bb = bg + 8 * i;
                float2 p0 = up2(acc[i][0]), p1 = up2(acc[i][1]);
                int c0 = cbase + 2 * cg;
                float v0 = p0.x + fcb[c0], v1 = p0.y + fcb[c0 + 1];
                float v2 = p1.x + fcb[c0 + 32], v3 = p1.y + fcb[c0 + 33];
                float* o = out + (size_t)bb * ((size_t)Tsz * Vsz) + (size_t)(step + 1) * Vsz;
                *(float2*)(o + c0) = make_float2(v0, v1);
                *(float2*)(o + c0 + 32) = make_float2(v2, v3);
                float bv = v0; int bc = c0;
                if (v1 > bv) { bv = v1; bc = c0 + 1; }
                if (v2 > bv) { bv = v2; bc = c0 + 32; }
                if (v3 > bv) { bv = v3; bc = c0 + 33; }
                atomicMax(&sk[bb], packkey(bv, bc));
            }
            __syncthreads();
            if (tid < 32) atomicMax(&g_amax[tid], sk[tid]);
        }
        gbar();
    }
}

extern "C" void kernel_launch(void* const* d_in, const int* in_sizes, int n_in,
                              void* d_out, int out_size) {
    const int* src = (const int*)d_in[0];
    const int* trg = (const int*)d_in[1];
    const float* enc_emb = (const float*)d_in[3];
    const float* eW0 = (const float*)d_in[4];
    const float* eU0 = (const float*)d_in[5];
    const float* ebi0 = (const float*)d_in[6];
    const float* ebh0 = (const float*)d_in[7];
    const float* eW1 = (const float*)d_in[8];
    const float* eU1 = (const float*)d_in[9];
    const float* ebi1 = (const float*)d_in[10];
    const float* ebh1 = (const float*)d_in[11];
    const float* demb = (const float*)d_in[12];
    const float* dW0 = (const float*)d_in[13];
    const float* dU0 = (const float*)d_in[14];
    const float* dbi0 = (const float*)d_in[15];
    const float* dbh0 = (const float*)d_in[16];
    const float* dW1 = (const float*)d_in[17];
    const float* dU1 = (const float*)d_in[18];
    const float* dbi1 = (const float*)d_in[19];
    const float* dbh1 = (const float*)d_in[20];
    const float* fcW = (const float*)d_in[21];
    const float* fcb = (const float*)d_in[22];
    float* out = (float*)d_out;

    k_init<<<128, 256>>>(trg);
    k_zero0<<<(Bsz * Vsz + 255) / 256, 256>>>(out);

    k_big<<<dim3(48, 128), 128>>>(enc_emb, src, eW0, ebi0, Esz, 1);
    k_enc<<<NBLK, 128>>>(eU0, ebh0, 0);
    k_big<<<dim3(48, 128), 128>>>(nullptr, nullptr, eW1, ebi1, Hsz, 0);
    k_enc<<<NBLK, 128>>>(eU1, ebh1, 1);
    k_dec<<<NBLK, 128>>>(demb, dW0, dU0, dbi0, dbh0,
                         dW1, dU1, dbi1, dbh1, fcW, fcb, out);
}

// round 6
// speedup vs baseline: 1.2705x; 1.2705x over previous
#include <cuda_runtime.h>
#include <math.h>

typedef unsigned long long ull;

#define Bsz 32
#define Ssz 128
#define Tsz 128
#define Hsz 1024
#define G3H 3072
#define Esz 512
#define Vsz 32000
#define NBLK 296

// ---------------- static scratch ----------------
__device__ float g_gi[(size_t)Ssz * Bsz * G3H];    // bulk input-gates (bias folded)
__device__ float g_ys0[(size_t)Ssz * Bsz * Hsz];   // encoder layer0 outputs
__device__ float g_px[(size_t)16 * Bsz * G3H];     // split-K partials (x-part)
__device__ float g_ph[(size_t)16 * Bsz * G3H];     // split-K partials (h-part)
__device__ float g_pfc[(size_t)8 * Bsz * Vsz];     // FC split-K partials
__device__ float g_h1[Bsz * Hsz];
__device__ float g_h2[Bsz * Hsz];
__device__ int g_tok[Bsz];
__device__ ull g_amax[Bsz];
__device__ unsigned g_bar_count = 0;
__device__ volatile unsigned g_bar_gen = 0;

// ---------------- helpers ----------------
__device__ __forceinline__ ull ffma2(ull a, ull b, ull c) {
    ull d;
    asm("fma.rn.f32x2 %0, %1, %2, %3;" : "=l"(d) : "l"(a), "l"(b), "l"(c));
    return d;
}
__device__ __forceinline__ float2 up2(ull v) {
    float2 f;
    asm("mov.b64 {%0, %1}, %2;" : "=f"(f.x), "=f"(f.y) : "l"(v));
    return f;
}
__device__ __forceinline__ ull packkey(float v, int c) {
    unsigned b = __float_as_uint(v);
    b = (b & 0x80000000u) ? ~b : (b | 0x80000000u);
    return ((ull)b << 32) | (ull)(0xFFFFFFFFu - (unsigned)c);
}

// grid barrier: sense-reversing, generation monotonic across graph replays
__device__ __forceinline__ void gbar() {
    __syncthreads();
    __threadfence();
    if (threadIdx.x == 0) {
        unsigned gen = g_bar_gen;
        if (atomicAdd(&g_bar_count, 1u) == gridDim.x - 1u) {
            g_bar_count = 0u;
            __threadfence();
            g_bar_gen = gen + 1u;
        } else {
            while (g_bar_gen == gen) __nanosleep(32);
        }
    }
    __syncthreads();
    __threadfence();
}

// ---------------- GEMM task: 32 rows x 128 cols, K-parity FFMA2 ----------------
// Thread (bg=tid>>4, cg=tid&15): rows {bg+8i}, cols {cbase+cg+16j}.
// acc[i][j] is f32x2 over k-parity; final = .x + .y.
// A: raw rows in As[32][68]; W: raw rows (output-col major) in Ws[128][66].
__device__ __noinline__ void gemm_task(
    const float* __restrict__ A, const int* __restrict__ toks, int lda,
    const float* __restrict__ W, int ldw,
    int kbase, int nchunk, int cbase,
    float* __restrict__ outp, int out_ld, const float* __restrict__ bias,
    float (*As)[68], float (*Ws)[66])
{
    const int tid = threadIdx.x;
    const int bg = tid >> 4, cg = tid & 15;
    ull acc[4][8];
#pragma unroll
    for (int i = 0; i < 4; i++)
#pragma unroll
        for (int j = 0; j < 8; j++) acc[i][j] = 0ull;

    for (int ch = 0; ch < nchunk; ch++) {
        const int kb = kbase + ch * 64;
        __syncthreads();
#pragma unroll
        for (int r = 0; r < 4; r++) {   // A: 32 rows x 64 k
            int f4 = tid + r * 128, row = f4 >> 4, kq = f4 & 15;
            const float* src = toks ? (A + (size_t)toks[row] * lda)
                                    : (A + (size_t)row * lda);
            float4 v = *(const float4*)(src + kb + kq * 4);
            *(float4*)&As[row][kq * 4] = v;
        }
#pragma unroll 4
        for (int r = 0; r < 16; r++) {  // W: 128 cols x 64 k
            int f4 = tid + r * 128, c = f4 >> 4, kq = f4 & 15;
            float4 v = *(const float4*)(W + (size_t)(cbase + c) * ldw + kb + kq * 4);
            *(float2*)&Ws[c][kq * 4] = make_float2(v.x, v.y);
            *(float2*)&Ws[c][kq * 4 + 2] = make_float2(v.z, v.w);
        }
        __syncthreads();
#pragma unroll 4
        for (int g = 0; g < 16; g++) {
            const int k0 = g * 4;
            ull a0l = *(const ull*)&As[bg][k0],      a0h = *(const ull*)&As[bg][k0 + 2];
            ull a1l = *(const ull*)&As[bg + 8][k0],  a1h = *(const ull*)&As[bg + 8][k0 + 2];
            ull a2l = *(const ull*)&As[bg + 16][k0], a2h = *(const ull*)&As[bg + 16][k0 + 2];
            ull a3l = *(const ull*)&As[bg + 24][k0], a3h = *(const ull*)&As[bg + 24][k0 + 2];
#pragma unroll
            for (int j = 0; j < 8; j++) {
                ull w0 = *(const ull*)&Ws[cg + 16 * j][k0];
                ull w1 = *(const ull*)&Ws[cg + 16 * j][k0 + 2];
                acc[0][j] = ffma2(a0l, w0, acc[0][j]);
                acc[1][j] = ffma2(a1l, w0, acc[1][j]);
                acc[2][j] = ffma2(a2l, w0, acc[2][j]);
                acc[3][j] = ffma2(a3l, w0, acc[3][j]);
                acc[0][j] = ffma2(a0h, w1, acc[0][j]);
                acc[1][j] = ffma2(a1h, w1, acc[1][j]);
                acc[2][j] = ffma2(a2h, w1, acc[2][j]);
                acc[3][j] = ffma2(a3h, w1, acc[3][j]);
            }
        }
    }
#pragma unroll
    for (int i = 0; i < 4; i++) {
        float* o = outp + (size_t)(bg + 8 * i) * out_ld + cbase;
#pragma unroll
        for (int j = 0; j < 8; j++) {
            float2 p = up2(acc[i][j]);
            float v = p.x + p.y;
            int c = cg + 16 * j;
            if (bias) v += bias[cbase + c];
            o[c] = v;
        }
    }
}

// ---------------- GRU gates + state update ----------------
__device__ __forceinline__ void gru_gates(const float* gi_pre, int nx,
                                          const float* bih, int nh,
                                          const float* bhh,
                                          float* h, float* ys) {
    for (int idx = blockIdx.x * 128 + threadIdx.x; idx < Bsz * Hsz; idx += NBLK * 128) {
        int b = idx >> 10, j = idx & 1023;
        float ir, iz, in_;
        if (gi_pre) {
            const float* g = gi_pre + (size_t)b * G3H;
            ir = g[j]; iz = g[Hsz + j]; in_ = g[2 * Hsz + j];
        } else {
            ir = bih[j]; iz = bih[Hsz + j]; in_ = bih[2 * Hsz + j];
            for (int s = 0; s < nx; s++) {
                const float* p = g_px + (size_t)s * Bsz * G3H + (size_t)b * G3H;
                ir += p[j]; iz += p[Hsz + j]; in_ += p[2 * Hsz + j];
            }
        }
        float hr = bhh[j], hz = bhh[Hsz + j], hn = bhh[2 * Hsz + j];
        for (int s = 0; s < nh; s++) {
            const float* p = g_ph + (size_t)s * Bsz * G3H + (size_t)b * G3H;
            hr += p[j]; hz += p[Hsz + j]; hn += p[2 * Hsz + j];
        }
        float r = 1.f / (1.f + expf(-(ir + hr)));
        float z = 1.f / (1.f + expf(-(iz + hz)));
        float n = tanhf(in_ + r * hn);
        float hv = h[idx];
        float hnew = (1.f - z) * n + z * hv;
        h[idx] = hnew;
        if (ys) ys[idx] = hnew;
    }
}

// ---------------- kernels ----------------
__global__ void k_init(const int* __restrict__ trg) {
    int i = blockIdx.x * blockDim.x + threadIdx.x;
    if (i < Bsz * Hsz) { g_h1[i] = 0.f; g_h2[i] = 0.f; }
    if (i < Bsz) { g_tok[i] = trg[i * Tsz]; g_amax[i] = 0ull; }
}

__global__ void k_zero0(float* __restrict__ out) {
    int i = blockIdx.x * blockDim.x + threadIdx.x;
    if (i < Bsz * Vsz) {
        int b = i / Vsz, v = i - b * Vsz;
        out[(size_t)b * ((size_t)Tsz * Vsz) + v] = 0.f;
    }
}

// bulk input-gate GEMM over all timesteps: grid (24, 128)
__global__ void __launch_bounds__(128, 2) k_big(
    const float* __restrict__ emb, const int* __restrict__ src,
    const float* __restrict__ W, const float* __restrict__ bias,
    int K, int gather)
{
    __shared__ float As[32][68];
    __shared__ float Ws[128][66];
    __shared__ int s_tok[32];
    int tid = threadIdx.x, tblk = blockIdx.y, cbase = blockIdx.x * 128;
    const float* A; int lda; const int* tp = nullptr;
    if (gather) {
        if (tid < 32) s_tok[tid] = src[tid * Ssz + tblk];
        __syncthreads();
        tp = s_tok; A = emb; lda = Esz;
    } else {
        A = g_ys0 + (size_t)tblk * Bsz * Hsz; lda = Hsz;
    }
    gemm_task(A, tp, lda, W, K, 0, K / 64, cbase,
              g_gi + (size_t)tblk * Bsz * G3H, G3H, bias, As, Ws);
}

// persistent encoder layer: 128 recurrent steps
__global__ void __launch_bounds__(128, 2) k_enc(
    const float* __restrict__ U, const float* __restrict__ bhh, int layer)
{
    __shared__ float As[32][68];
    __shared__ float Ws[128][66];
    int bid = blockIdx.x;
    float* h = layer ? g_h2 : g_h1;
    for (int t = 0; t < Ssz; t++) {
        for (int task = bid; task < 384; task += NBLK) {   // 24 ct x 16 slices
            int ct = task % 24, s = task / 24;
            gemm_task(h, nullptr, Hsz, U, Hsz, s * 64, 1, ct * 128,
                      g_ph + (size_t)s * Bsz * G3H, G3H, nullptr, As, Ws);
        }
        gbar();
        gru_gates(g_gi + (size_t)t * Bsz * G3H, 0, nullptr, 16, bhh,
                  h, layer ? nullptr : (g_ys0 + (size_t)t * Bsz * Hsz));
        gbar();
    }
}

// persistent decoder: 127 greedy steps, 6 phases per step
__global__ void __launch_bounds__(128, 2) k_dec(
    const float* __restrict__ demb,
    const float* __restrict__ dW0, const float* __restrict__ dU0,
    const float* __restrict__ dbi0, const float* __restrict__ dbh0,
    const float* __restrict__ dW1, const float* __restrict__ dU1,
    const float* __restrict__ dbi1, const float* __restrict__ dbh1,
    const float* __restrict__ fcW, const float* __restrict__ fcb,
    float* __restrict__ out)
{
    __shared__ float As[32][68];
    __shared__ float Ws[128][66];
    __shared__ int s_tok[32];
    __shared__ ull sk[32];
    int tid = threadIdx.x, bid = blockIdx.x;
    for (int step = 0; step < Tsz - 1; step++) {
        if (tid < 32)
            s_tok[tid] = (step == 0)
                ? g_tok[tid]
                : (int)(0xFFFFFFFFu - (unsigned)(g_amax[tid] & 0xFFFFFFFFull));
        __syncthreads();
        // P1: layer0 gi (emb gather, 8 slices) + gh (h1, 16 slices): 576 tasks
        for (int task = bid; task < 576; task += NBLK) {
            if (task < 192) {
                int ct = task % 24, s = task / 24;
                gemm_task(demb, s_tok, Esz, dW0, Esz, s * 64, 1, ct * 128,
                          g_px + (size_t)s * Bsz * G3H, G3H, nullptr, As, Ws);
            } else {
                int t2 = task - 192, ct = t2 % 24, s = t2 / 24;
                gemm_task(g_h1, nullptr, Hsz, dU0, Hsz, s * 64, 1, ct * 128,
                          g_ph + (size_t)s * Bsz * G3H, G3H, nullptr, As, Ws);
            }
        }
        gbar();
        // P2: gates -> h1 ; reset argmax accumulator
        gru_gates(nullptr, 8, dbi0, 16, dbh0, g_h1, nullptr);
        if (bid == 0 && tid < 32) g_amax[tid] = 0ull;
        gbar();
        // P3: layer1 gi (h1) + gh (h2): 768 tasks
        for (int task = bid; task < 768; task += NBLK) {
            if (task < 384) {
                int ct = task % 24, s = task / 24;
                gemm_task(g_h1, nullptr, Hsz, dW1, Hsz, s * 64, 1, ct * 128,
                          g_px + (size_t)s * Bsz * G3H, G3H, nullptr, As, Ws);
            } else {
                int t2 = task - 384, ct = t2 % 24, s = t2 / 24;
                gemm_task(g_h2, nullptr, Hsz, dU1, Hsz, s * 64, 1, ct * 128,
                          g_ph + (size_t)s * Bsz * G3H, G3H, nullptr, As, Ws);
            }
        }
        gbar();
        // P4: gates -> h2
        gru_gates(nullptr, 16, dbi1, 16, dbh1, g_h2, nullptr);
        gbar();
        // P5: FC split-K partials: 250 coltiles x 8 slices (128-wide, 2 chunks)
        for (int task = bid; task < 2000; task += NBLK) {
            int ct = task >> 3, s = task & 7;
            gemm_task(g_h2, nullptr, Hsz, fcW, Hsz, s * 128, 2, ct * 128,
                      g_pfc + (size_t)s * Bsz * Vsz, Vsz, nullptr, As, Ws);
        }
        gbar();
        // P6: reduce partials + bias, store logits, deterministic argmax
        if (tid < 32) sk[tid] = 0ull;
        __syncthreads();
        for (int unit = bid * 128 + tid; unit < Bsz * (Vsz / 4); unit += NBLK * 128) {
            int row = unit / (Vsz / 4), c4 = unit - row * (Vsz / 4);
            int c = c4 * 4;
            float4 sacc = *(const float4*)&fcb[c];
            for (int s = 0; s < 8; s++) {
                const float4 p = *(const float4*)&g_pfc[(size_t)s * Bsz * Vsz +
                                                        (size_t)row * Vsz + c];
                sacc.x += p.x; sacc.y += p.y; sacc.z += p.z; sacc.w += p.w;
            }
            *(float4*)&out[(size_t)row * ((size_t)Tsz * Vsz) +
                           (size_t)(step + 1) * Vsz + c] = sacc;
            float bv = sacc.x; int bc = c;
            if (sacc.y > bv) { bv = sacc.y; bc = c + 1; }
            if (sacc.z > bv) { bv = sacc.z; bc = c + 2; }
            if (sacc.w > bv) { bv = sacc.w; bc = c + 3; }
            atomicMax(&sk[row], packkey(bv, bc));
        }
        __syncthreads();
        if (tid < 32 && sk[tid]) atomicMax(&g_amax[tid], sk[tid]);
        gbar();
    }
}

extern "C" void kernel_launch(void* const* d_in, const int* in_sizes, int n_in,
                              void* d_out, int out_size) {
    const int* src = (const int*)d_in[0];
    const int* trg = (const int*)d_in[1];
    const float* enc_emb = (const float*)d_in[3];
    const float* eW0 = (const float*)d_in[4];
    const float* eU0 = (const float*)d_in[5];
    const float* ebi0 = (const float*)d_in[6];
    const float* ebh0 = (const float*)d_in[7];
    const float* eW1 = (const float*)d_in[8];
    const float* eU1 = (const float*)d_in[9];
    const float* ebi1 = (const float*)d_in[10];
    const float* ebh1 = (const float*)d_in[11];
    const float* demb = (const float*)d_in[12];
    const float* dW0 = (const float*)d_in[13];
    const float* dU0 = (const float*)d_in[14];
    const float* dbi0 = (const float*)d_in[15];
    const float* dbh0 = (const float*)d_in[16];
    const float* dW1 = (const float*)d_in[17];
    const float* dU1 = (const float*)d_in[18];
    const float* dbi1 = (const float*)d_in[19];
    const float* dbh1 = (const float*)d_in[20];
    const float* fcW = (const float*)d_in[21];
    const float* fcb = (const float*)d_in[22];
    float* out = (float*)d_out;

    k_init<<<128, 256>>>(trg);
    k_zero0<<<(Bsz * Vsz + 255) / 256, 256>>>(out);

    k_big<<<dim3(24, 128), 128>>>(enc_emb, src, eW0, ebi0, Esz, 1);
    k_enc<<<NBLK, 128>>>(eU0, ebh0, 0);
    k_big<<<dim3(24, 128), 128>>>(nullptr, nullptr, eW1, ebi1, Hsz, 0);
    k_enc<<<NBLK, 128>>>(eU1, ebh1, 1);
    k_dec<<<NBLK, 128>>>(demb, dW0, dU0, dbi0, dbh0,
                         dW1, dU1, dbi1, dbh1, fcW, fcb, out);
}

// round 9
// speedup vs baseline: 1.3483x; 1.0612x over previous
#include <cuda_runtime.h>
#include <math.h>

typedef unsigned long long ull;

#define Bsz 32
#define Ssz 128
#define Tsz 128
#define Hsz 1024
#define G3H 3072
#define Esz 512
#define Vsz 32000
#define NBLK 444
#define NBUCKET 37
#define BUCKSZ 12

// ---------------- static scratch ----------------
__device__ float g_gi[(size_t)Ssz * Bsz * G3H];    // bulk input-gates (bias folded)
__device__ float g_ys0[(size_t)Ssz * Bsz * Hsz];   // encoder layer0 outputs
__device__ float g_px[(size_t)16 * Bsz * G3H];     // split-K partials (x-part)
__device__ float g_ph[(size_t)16 * Bsz * G3H];     // split-K partials (h-part)
__device__ float g_pfc[(size_t)8 * Bsz * Vsz];     // FC split-K partials
__device__ float g_h1[Bsz * Hsz];
__device__ float g_h2[Bsz * Hsz];
__device__ int g_tok[Bsz];
__device__ ull g_amax[Bsz];
__device__ unsigned g_bar_c1[NBUCKET * 32];        // bucket counters, 128B apart
__device__ unsigned g_bar_c2;
__device__ unsigned g_bar_gen;

// ---------------- helpers ----------------
__device__ __forceinline__ ull ffma2(ull a, ull b, ull c) {
    ull d;
    asm("fma.rn.f32x2 %0, %1, %2, %3;" : "=l"(d) : "l"(a), "l"(b), "l"(c));
    return d;
}
__device__ __forceinline__ float2 up2(ull v) {
    float2 f;
    asm("mov.b64 {%0, %1}, %2;" : "=f"(f.x), "=f"(f.y) : "l"(v));
    return f;
}
__device__ __forceinline__ ull packkey(float v, int c) {
    unsigned b = __float_as_uint(v);
    b = (b & 0x80000000u) ? ~b : (b | 0x80000000u);
    return ((ull)b << 32) | (ull)(0xFFFFFFFFu - (unsigned)c);
}

// grid barrier: 2-level (12/bucket x 37 buckets), modular counters (no resets),
// generation monotonic across graph replays; fence-complete release chain.
__device__ __forceinline__ void gbar() {
    __syncthreads();
    __threadfence();
    if (threadIdx.x == 0) {
        unsigned gen;
        asm volatile("ld.acquire.gpu.u32 %0, [%1];"
                     : "=r"(gen) : "l"(&g_bar_gen) : "memory");
        unsigned b = blockIdx.x % NBUCKET;
        bool master = false;
        if (atomicAdd(&g_bar_c1[b * 32], 1u) % BUCKSZ == BUCKSZ - 1u) {
            __threadfence();   // cumulativity: bucket writers' data -> c2 chain
            master = (atomicAdd(&g_bar_c2, 1u) % NBUCKET == NBUCKET - 1u);
        }
        if (master) {
            __threadfence();
            asm volatile("st.release.gpu.u32 [%0], %1;"
                         :: "l"(&g_bar_gen), "r"(gen + 1u) : "memory");
        } else {
            unsigned cur;
            while (true) {
                asm volatile("ld.acquire.gpu.u32 %0, [%1];"
                             : "=r"(cur) : "l"(&g_bar_gen) : "memory");
                if (cur != gen) break;
                __nanosleep(32);
            }
        }
    }
    __syncthreads();
    __threadfence();
}

// ---------------- GEMM task: 32 rows x 128 cols, K-parity FFMA2 ----------------
// ARITHMETIC IDENTICAL TO R6 (passing): do not change slice widths or sum order.
__device__ __noinline__ void gemm_task(
    const float* __restrict__ A, const int* __restrict__ toks, int lda,
    const float* __restrict__ W, int ldw,
    int kbase, int nchunk, int cbase,
    float* __restrict__ outp, int out_ld, const float* __restrict__ bias,
    float (*As)[68], float (*Ws)[66])
{
    const int tid = threadIdx.x;
    const int bg = tid >> 4, cg = tid & 15;
    ull acc[4][8];
#pragma unroll
    for (int i = 0; i < 4; i++)
#pragma unroll
        for (int j = 0; j < 8; j++) acc[i][j] = 0ull;

    for (int ch = 0; ch < nchunk; ch++) {
        const int kb = kbase + ch * 64;
        __syncthreads();
#pragma unroll
        for (int r = 0; r < 4; r++) {   // A: 32 rows x 64 k
            int f4 = tid + r * 128, row = f4 >> 4, kq = f4 & 15;
            const float* src = toks ? (A + (size_t)toks[row] * lda)
                                    : (A + (size_t)row * lda);
            float4 v = *(const float4*)(src + kb + kq * 4);
            *(float4*)&As[row][kq * 4] = v;
        }
#pragma unroll 4
        for (int r = 0; r < 16; r++) {  // W: 128 cols x 64 k
            int f4 = tid + r * 128, c = f4 >> 4, kq = f4 & 15;
            float4 v = *(const float4*)(W + (size_t)(cbase + c) * ldw + kb + kq * 4);
            *(float2*)&Ws[c][kq * 4] = make_float2(v.x, v.y);
            *(float2*)&Ws[c][kq * 4 + 2] = make_float2(v.z, v.w);
        }
        __syncthreads();
#pragma unroll 4
        for (int g = 0; g < 16; g++) {
            const int k0 = g * 4;
            ull a0l = *(const ull*)&As[bg][k0],      a0h = *(const ull*)&As[bg][k0 + 2];
            ull a1l = *(const ull*)&As[bg + 8][k0],  a1h = *(const ull*)&As[bg + 8][k0 + 2];
            ull a2l = *(const ull*)&As[bg + 16][k0], a2h = *(const ull*)&As[bg + 16][k0 + 2];
            ull a3l = *(const ull*)&As[bg + 24][k0], a3h = *(const ull*)&As[bg + 24][k0 + 2];
#pragma unroll
            for (int j = 0; j < 8; j++) {
                ull w0 = *(const ull*)&Ws[cg + 16 * j][k0];
                ull w1 = *(const ull*)&Ws[cg + 16 * j][k0 + 2];
                acc[0][j] = ffma2(a0l, w0, acc[0][j]);
                acc[1][j] = ffma2(a1l, w0, acc[1][j]);
                acc[2][j] = ffma2(a2l, w0, acc[2][j]);
                acc[3][j] = ffma2(a3l, w0, acc[3][j]);
                acc[0][j] = ffma2(a0h, w1, acc[0][j]);
                acc[1][j] = ffma2(a1h, w1, acc[1][j]);
                acc[2][j] = ffma2(a2h, w1, acc[2][j]);
                acc[3][j] = ffma2(a3h, w1, acc[3][j]);
            }
        }
    }
#pragma unroll
    for (int i = 0; i < 4; i++) {
        float* o = outp + (size_t)(bg + 8 * i) * out_ld + cbase;
#pragma unroll
        for (int j = 0; j < 8; j++) {
            float2 p = up2(acc[i][j]);
            float v = p.x + p.y;
            int c = cg + 16 * j;
            if (bias) v += bias[cbase + c];
            o[c] = v;
        }
    }
}

// ---------------- GRU gates + state update (R6 sum order) ----------------
__device__ __forceinline__ void gru_gates(const float* gi_pre, int nx,
                                          const float* bih, int nh,
                                          const float* bhh,
                                          float* h, float* ys) {
    for (int idx = blockIdx.x * 128 + threadIdx.x; idx < Bsz * Hsz; idx += NBLK * 128) {
        int b = idx >> 10, j = idx & 1023;
        float ir, iz, in_;
        if (gi_pre) {
            const float* g = gi_pre + (size_t)b * G3H;
            ir = g[j]; iz = g[Hsz + j]; in_ = g[2 * Hsz + j];
        } else {
            ir = bih[j]; iz = bih[Hsz + j]; in_ = bih[2 * Hsz + j];
            for (int s = 0; s < nx; s++) {
                const float* p = g_px + (size_t)s * Bsz * G3H + (size_t)b * G3H;
                ir += p[j]; iz += p[Hsz + j]; in_ += p[2 * Hsz + j];
            }
        }
        float hr = bhh[j], hz = bhh[Hsz + j], hn = bhh[2 * Hsz + j];
        for (int s = 0; s < nh; s++) {
            const float* p = g_ph + (size_t)s * Bsz * G3H + (size_t)b * G3H;
            hr += p[j]; hz += p[Hsz + j]; hn += p[2 * Hsz + j];
        }
        float r = 1.f / (1.f + expf(-(ir + hr)));
        float z = 1.f / (1.f + expf(-(iz + hz)));
        float n = tanhf(in_ + r * hn);
        float hv = h[idx];
        float hnew = (1.f - z) * n + z * hv;
        h[idx] = hnew;
        if (ys) ys[idx] = hnew;
    }
}

// ---------------- kernels ----------------
__global__ void k_init(const int* __restrict__ trg) {
    int i = blockIdx.x * blockDim.x + threadIdx.x;
    if (i < Bsz * Hsz) { g_h1[i] = 0.f; g_h2[i] = 0.f; }
    if (i < Bsz) { g_tok[i] = trg[i * Tsz]; g_amax[i] = 0ull; }
}

__global__ void k_zero0(float* __restrict__ out) {
    int i = blockIdx.x * blockDim.x + threadIdx.x;
    if (i < Bsz * Vsz) {
        int b = i / Vsz, v = i - b * Vsz;
        out[(size_t)b * ((size_t)Tsz * Vsz) + v] = 0.f;
    }
}

// bulk input-gate GEMM over all timesteps: grid (24, 128) [R6 arithmetic]
__global__ void __launch_bounds__(128, 3) k_big(
    const float* __restrict__ emb, const int* __restrict__ src,
    const float* __restrict__ W, const float* __restrict__ bias,
    int K, int gather)
{
    __shared__ float As[32][68];
    __shared__ float Ws[128][66];
    __shared__ int s_tok[32];
    int tid = threadIdx.x, tblk = blockIdx.y, cbase = blockIdx.x * 128;
    const float* A; int lda; const int* tp = nullptr;
    if (gather) {
        if (tid < 32) s_tok[tid] = src[tid * Ssz + tblk];
        __syncthreads();
        tp = s_tok; A = emb; lda = Esz;
    } else {
        A = g_ys0 + (size_t)tblk * Bsz * Hsz; lda = Hsz;
    }
    gemm_task(A, tp, lda, W, K, 0, K / 64, cbase,
              g_gi + (size_t)tblk * Bsz * G3H, G3H, bias, As, Ws);
}

// persistent encoder layer: 128 recurrent steps [R6 arithmetic: 16 slices of 64]
__global__ void __launch_bounds__(128, 3) k_enc(
    const float* __restrict__ U, const float* __restrict__ bhh, int layer)
{
    __shared__ float As[32][68];
    __shared__ float Ws[128][66];
    int bid = blockIdx.x;
    float* h = layer ? g_h2 : g_h1;
    for (int t = 0; t < Ssz; t++) {
        for (int task = bid; task < 384; task += NBLK) {   // 24 ct x 16 slices
            int ct = task % 24, s = task / 24;
            gemm_task(h, nullptr, Hsz, U, Hsz, s * 64, 1, ct * 128,
                      g_ph + (size_t)s * Bsz * G3H, G3H, nullptr, As, Ws);
        }
        gbar();
        gru_gates(g_gi + (size_t)t * Bsz * G3H, 0, nullptr, 16, bhh,
                  h, layer ? nullptr : (g_ys0 + (size_t)t * Bsz * Hsz));
        gbar();
    }
}

// persistent decoder: 127 greedy steps, 6 phases per step [R6 arithmetic]
__global__ void __launch_bounds__(128, 3) k_dec(
    const float* __restrict__ demb,
    const float* __restrict__ dW0, const float* __restrict__ dU0,
    const float* __restrict__ dbi0, const float* __restrict__ dbh0,
    const float* __restrict__ dW1, const float* __restrict__ dU1,
    const float* __restrict__ dbi1, const float* __restrict__ dbh1,
    const float* __restrict__ fcW, const float* __restrict__ fcb,
    float* __restrict__ out)
{
    __shared__ float As[32][68];
    __shared__ float Ws[128][66];
    __shared__ int s_tok[32];
    __shared__ ull sk[32];
    int tid = threadIdx.x, bid = blockIdx.x;
    for (int step = 0; step < Tsz - 1; step++) {
        if (tid < 32)
            s_tok[tid] = (step == 0)
                ? g_tok[tid]
                : (int)(0xFFFFFFFFu - (unsigned)(g_amax[tid] & 0xFFFFFFFFull));
        __syncthreads();
        // P1: L0 gi (emb gather, 8 slices of 64) + gh (h1, 16 slices): 576 tasks
        for (int task = bid; task < 576; task += NBLK) {
            if (task < 192) {
                int ct = task % 24, s = task / 24;
                gemm_task(demb, s_tok, Esz, dW0, Esz, s * 64, 1, ct * 128,
                          g_px + (size_t)s * Bsz * G3H, G3H, nullptr, As, Ws);
            } else {
                int t2 = task - 192, ct = t2 % 24, s = t2 / 24;
                gemm_task(g_h1, nullptr, Hsz, dU0, Hsz, s * 64, 1, ct * 128,
                          g_ph + (size_t)s * Bsz * G3H, G3H, nullptr, As, Ws);
            }
        }
        gbar();
        // P2: gates -> h1 ; reset argmax accumulator
        gru_gates(nullptr, 8, dbi0, 16, dbh0, g_h1, nullptr);
        if (bid == 0 && tid < 32) g_amax[tid] = 0ull;
        gbar();
        // P3: L1 gi (h1) + gh (h2): 768 tasks, 16 slices each
        for (int task = bid; task < 768; task += NBLK) {
            if (task < 384) {
                int ct = task % 24, s = task / 24;
                gemm_task(g_h1, nullptr, Hsz, dW1, Hsz, s * 64, 1, ct * 128,
                          g_px + (size_t)s * Bsz * G3H, G3H, nullptr, As, Ws);
            } else {
                int t2 = task - 384, ct = t2 % 24, s = t2 / 24;
                gemm_task(g_h2, nullptr, Hsz, dU1, Hsz, s * 64, 1, ct * 128,
                          g_ph + (size_t)s * Bsz * G3H, G3H, nullptr, As, Ws);
            }
        }
        gbar();
        // P4: gates -> h2
        gru_gates(nullptr, 16, dbi1, 16, dbh1, g_h2, nullptr);
        gbar();
        // P5: FC split-K partials: 250 coltiles x 8 slices (128-wide, 2 chunks)
        for (int task = bid; task < 2000; task += NBLK) {
            int ct = task >> 3, s = task & 7;
            gemm_task(g_h2, nullptr, Hsz, fcW, Hsz, s * 128, 2, ct * 128,
                      g_pfc + (size_t)s * Bsz * Vsz, Vsz, nullptr, As, Ws);
        }
        gbar();
        // P6: reduce partials + bias, store logits, deterministic argmax
        if (tid < 32) sk[tid] = 0ull;
        __syncthreads();
        for (int unit = bid * 128 + tid; unit < Bsz * (Vsz / 4); unit += NBLK * 128) {
            int row = unit / (Vsz / 4), c4 = unit - row * (Vsz / 4);
            int c = c4 * 4;
            float4 sacc = *(const float4*)&fcb[c];
            for (int s = 0; s < 8; s++) {
                const float4 p = *(const float4*)&g_pfc[(size_t)s * Bsz * Vsz +
                                                        (size_t)row * Vsz + c];
                sacc.x += p.x; sacc.y += p.y; sacc.z += p.z; sacc.w += p.w;
            }
            *(float4*)&out[(size_t)row * ((size_t)Tsz * Vsz) +
                           (size_t)(step + 1) * Vsz + c] = sacc;
            float bv = sacc.x; int bc = c;
            if (sacc.y > bv) { bv = sacc.y; bc = c + 1; }
            if (sacc.z > bv) { bv = sacc.z; bc = c + 2; }
            if (sacc.w > bv) { bv = sacc.w; bc = c + 3; }
            atomicMax(&sk[row], packkey(bv, bc));
        }
        __syncthreads();
        if (tid < 32 && sk[tid]) atomicMax(&g_amax[tid], sk[tid]);
        gbar();
    }
}

extern "C" void kernel_launch(void* const* d_in, const int* in_sizes, int n_in,
                              void* d_out, int out_size) {
    const int* src = (const int*)d_in[0];
    const int* trg = (const int*)d_in[1];
    const float* enc_emb = (const float*)d_in[3];
    const float* eW0 = (const float*)d_in[4];
    const float* eU0 = (const float*)d_in[5];
    const float* ebi0 = (const float*)d_in[6];
    const float* ebh0 = (const float*)d_in[7];
    const float* eW1 = (const float*)d_in[8];
    const float* eU1 = (const float*)d_in[9];
    const float* ebi1 = (const float*)d_in[10];
    const float* ebh1 = (const float*)d_in[11];
    const float* demb = (const float*)d_in[12];
    const float* dW0 = (const float*)d_in[13];
    const float* dU0 = (const float*)d_in[14];
    const float* dbi0 = (const float*)d_in[15];
    const float* dbh0 = (const float*)d_in[16];
    const float* dW1 = (const float*)d_in[17];
    const float* dU1 = (const float*)d_in[18];
    const float* dbi1 = (const float*)d_in[19];
    const float* dbh1 = (const float*)d_in[20];
    const float* fcW = (const float*)d_in[21];
    const float* fcb = (const float*)d_in[22];
    float* out = (float*)d_out;

    k_init<<<128, 256>>>(trg);
    k_zero0<<<(Bsz * Vsz + 255) / 256, 256>>>(out);

    k_big<<<dim3(24, 128), 128>>>(enc_emb, src, eW0, ebi0, Esz, 1);
    k_enc<<<NBLK, 128>>>(eU0, ebh0, 0);
    k_big<<<dim3(24, 128), 128>>>(nullptr, nullptr, eW1, ebi1, Hsz, 0);
    k_enc<<<NBLK, 128>>>(eU1, ebh1, 1);
    k_dec<<<NBLK, 128>>>(demb, dW0, dU0, dbi0, dbh0,
                         dW1, dU1, dbi1, dbh1, fcW, fcb, out);
}

// round 10
// speedup vs baseline: 1.5418x; 1.1435x over previous
#include <cuda_runtime.h>
#include <math.h>

typedef unsigned long long ull;

#define Bsz 32
#define Ssz 128
#define Tsz 128
#define Hsz 1024
#define G3H 3072
#define Esz 512
#define Vsz 32000
#define NBLK_ENC 444
#define NBLK_DEC 296
#define NBUCKET 37

// ---------------- static scratch ----------------
__device__ float g_gi[(size_t)Ssz * Bsz * G3H];
__device__ float g_ys0[(size_t)Ssz * Bsz * Hsz];
__device__ float g_px[(size_t)16 * Bsz * G3H];
__device__ float g_ph[(size_t)16 * Bsz * G3H];
__device__ float g_pfc[(size_t)8 * Bsz * Vsz];
__device__ float g_h1[Bsz * Hsz];
__device__ float g_h2[Bsz * Hsz];
__device__ int g_tok[Bsz];
__device__ ull g_amax[Bsz];
__device__ unsigned g_bar_c1[NBUCKET * 32];
__device__ unsigned g_bar_c2;
__device__ unsigned g_bar_gen;

// ---------------- helpers ----------------
__device__ __forceinline__ ull ffma2(ull a, ull b, ull c) {
    ull d;
    asm("fma.rn.f32x2 %0, %1, %2, %3;" : "=l"(d) : "l"(a), "l"(b), "l"(c));
    return d;
}
__device__ __forceinline__ float2 up2(ull v) {
    float2 f;
    asm("mov.b64 {%0, %1}, %2;" : "=f"(f.x), "=f"(f.y) : "l"(v));
    return f;
}
__device__ __forceinline__ ull packkey(float v, int c) {
    unsigned b = __float_as_uint(v);
    b = (b & 0x80000000u) ? ~b : (b | 0x80000000u);
    return ((ull)b << 32) | (ull)(0xFFFFFFFFu - (unsigned)c);
}
__device__ __forceinline__ void cp16(void* dst, const void* src) {
    unsigned s = (unsigned)__cvta_generic_to_shared(dst);
    asm volatile("cp.async.cg.shared.global [%0], [%1], 16;" :: "r"(s), "l"(src));
}

// grid barrier: 2-level buckets, runtime bucket size (= gridDim.x/37),
// modular counters (offset-tolerant), monotonic gen, fence-complete.
__device__ __forceinline__ void gbar() {
    __syncthreads();
    __threadfence();
    if (threadIdx.x == 0) {
        unsigned gen;
        asm volatile("ld.acquire.gpu.u32 %0, [%1];"
                     : "=r"(gen) : "l"(&g_bar_gen) : "memory");
        unsigned bsz = gridDim.x / NBUCKET;
        unsigned b = blockIdx.x % NBUCKET;
        bool master = false;
        if (atomicAdd(&g_bar_c1[b * 32], 1u) % bsz == bsz - 1u) {
            __threadfence();
            master = (atomicAdd(&g_bar_c2, 1u) % NBUCKET == NBUCKET - 1u);
        }
        if (master) {
            __threadfence();
            asm volatile("st.release.gpu.u32 [%0], %1;"
                         :: "l"(&g_bar_gen), "r"(gen + 1u) : "memory");
        } else {
            unsigned cur;
            while (true) {
                asm volatile("ld.acquire.gpu.u32 %0, [%1];"
                             : "=r"(cur) : "l"(&g_bar_gen) : "memory");
                if (cur != gen) break;
                __nanosleep(32);
            }
        }
    }
    __syncthreads();
    __threadfence();
}

// ---------------- shared inner compute: 64-k chunk, K-parity FFMA2 ----------------
// ARITHMETIC FROZEN (R6/R9): k ascending, parity split, final .x+.y.
template <int LDW>
__device__ __forceinline__ void compute64(const float (*As)[68], const float (*Ws)[LDW],
                                          ull acc[4][8], int bg, int cg) {
#pragma unroll 4
    for (int g = 0; g < 16; g++) {
        const int k0 = g * 4;
        ull a0l = *(const ull*)&As[bg][k0],      a0h = *(const ull*)&As[bg][k0 + 2];
        ull a1l = *(const ull*)&As[bg + 8][k0],  a1h = *(const ull*)&As[bg + 8][k0 + 2];
        ull a2l = *(const ull*)&As[bg + 16][k0], a2h = *(const ull*)&As[bg + 16][k0 + 2];
        ull a3l = *(const ull*)&As[bg + 24][k0], a3h = *(const ull*)&As[bg + 24][k0 + 2];
#pragma unroll
        for (int j = 0; j < 8; j++) {
            ull w0 = *(const ull*)&Ws[cg + 16 * j][k0];
            ull w1 = *(const ull*)&Ws[cg + 16 * j][k0 + 2];
            acc[0][j] = ffma2(a0l, w0, acc[0][j]);
            acc[1][j] = ffma2(a1l, w0, acc[1][j]);
            acc[2][j] = ffma2(a2l, w0, acc[2][j]);
            acc[3][j] = ffma2(a3l, w0, acc[3][j]);
            acc[0][j] = ffma2(a0h, w1, acc[0][j]);
            acc[1][j] = ffma2(a1h, w1, acc[1][j]);
            acc[2][j] = ffma2(a2h, w1, acc[2][j]);
            acc[3][j] = ffma2(a3h, w1, acc[3][j]);
        }
    }
}

// ---------------- synchronous GEMM task (encoder/bulk; R9 verbatim path) --------
__device__ __noinline__ void gemm_task(
    const float* __restrict__ A, const int* __restrict__ toks, int lda,
    const float* __restrict__ W, int ldw,
    int kbase, int nchunk, int cbase,
    float* __restrict__ outp, int out_ld, const float* __restrict__ bias,
    float (*As)[68], float (*Ws)[66])
{
    const int tid = threadIdx.x;
    const int bg = tid >> 4, cg = tid & 15;
    ull acc[4][8];
#pragma unroll
    for (int i = 0; i < 4; i++)
#pragma unroll
        for (int j = 0; j < 8; j++) acc[i][j] = 0ull;

    for (int ch = 0; ch < nchunk; ch++) {
        const int kb = kbase + ch * 64;
        __syncthreads();
#pragma unroll
        for (int r = 0; r < 4; r++) {
            int f4 = tid + r * 128, row = f4 >> 4, kq = f4 & 15;
            const float* src = toks ? (A + (size_t)toks[row] * lda)
                                    : (A + (size_t)row * lda);
            float4 v = *(const float4*)(src + kb + kq * 4);
            *(float4*)&As[row][kq * 4] = v;
        }
#pragma unroll 4
        for (int r = 0; r < 16; r++) {
            int f4 = tid + r * 128, c = f4 >> 4, kq = f4 & 15;
            float4 v = *(const float4*)(W + (size_t)(cbase + c) * ldw + kb + kq * 4);
            *(float2*)&Ws[c][kq * 4] = make_float2(v.x, v.y);
            *(float2*)&Ws[c][kq * 4 + 2] = make_float2(v.z, v.w);
        }
        __syncthreads();
        compute64<66>(As, Ws, acc, bg, cg);
    }
#pragma unroll
    for (int i = 0; i < 4; i++) {
        float* o = outp + (size_t)(bg + 8 * i) * out_ld + cbase;
#pragma unroll
        for (int j = 0; j < 8; j++) {
            float2 p = up2(acc[i][j]);
            float v = p.x + p.y;
            int c = cg + 16 * j;
            if (bias) v += bias[cbase + c];
            o[c] = v;
        }
    }
}

// ---------------- pipelined decoder phase executor ----------------
struct TD {
    const float* A; const int* toks; const float* W; float* outp;
    int lda, ldw, kbase, nch, cbase, out_ld;
};

struct DecCtx {
    const float *demb, *dW0, *dU0, *dW1, *dU1, *fcW;
    const int* stok;
};

__device__ __forceinline__ TD dec_task(int phase, int t, const DecCtx& c) {
    TD d;
    if (phase == 0) {               // P1: 576 tasks
        if (t < 192) {
            int ct = t % 24, s = t / 24;                     // gi: 8 slices of 64
            d = {c.demb, c.stok, c.dW0, g_px + (size_t)s * Bsz * G3H,
                 Esz, Esz, s * 64, 1, ct * 128, G3H};
        } else {
            int t2 = t - 192, ct = t2 % 24, s = t2 / 24;     // gh: 16 slices of 64
            d = {g_h1, nullptr, c.dU0, g_ph + (size_t)s * Bsz * G3H,
                 Hsz, Hsz, s * 64, 1, ct * 128, G3H};
        }
    } else if (phase == 1) {        // P3: 768 tasks
        if (t < 384) {
            int ct = t % 24, s = t / 24;
            d = {g_h1, nullptr, c.dW1, g_px + (size_t)s * Bsz * G3H,
                 Hsz, Hsz, s * 64, 1, ct * 128, G3H};
        } else {
            int t2 = t - 384, ct = t2 % 24, s = t2 / 24;
            d = {g_h2, nullptr, c.dU1, g_ph + (size_t)s * Bsz * G3H,
                 Hsz, Hsz, s * 64, 1, ct * 128, G3H};
        }
    } else {                        // P5: 2000 FC tasks, 2 chunks each
        int ct = t >> 3, s = t & 7;
        d = {g_h2, nullptr, c.fcW, g_pfc + (size_t)s * Bsz * Vsz,
             Hsz, Hsz, s * 128, 2, ct * 128, Vsz};
    }
    return d;
}

__device__ __forceinline__ void issue_chunk(const TD& t, int ch,
                                            float (*As)[68], float (*Ws)[68], int tid) {
    const int kb = t.kbase + ch * 64;
#pragma unroll
    for (int r = 0; r < 4; r++) {
        int f4 = tid + r * 128, row = f4 >> 4, kq = f4 & 15;
        const float* src = t.toks ? (t.A + (size_t)t.toks[row] * t.lda)
                                  : (t.A + (size_t)row * t.lda);
        cp16(&As[row][kq * 4], src + kb + kq * 4);
    }
#pragma unroll 4
    for (int r = 0; r < 16; r++) {
        int f4 = tid + r * 128, c = f4 >> 4, kq = f4 & 15;
        cp16(&Ws[c][kq * 4], t.W + (size_t)(t.cbase + c) * t.ldw + kb + kq * 4);
    }
    asm volatile("cp.async.commit_group;" ::: "memory");
}

__device__ __noinline__ void run_phase(int phase, int ntask, const DecCtx& c,
                                       float (*AsB)[32][68], float (*WsB)[128][68]) {
    const int tid = threadIdx.x;
    const int bg = tid >> 4, cg = tid & 15;
    int i = blockIdx.x;
    if (i >= ntask) return;
    TD cur = dec_task(phase, i, c);
    int ch = 0, b = 0;
    issue_chunk(cur, 0, AsB[0], WsB[0], tid);
    ull acc[4][8];
#pragma unroll
    for (int x = 0; x < 4; x++)
#pragma unroll
        for (int y = 0; y < 8; y++) acc[x][y] = 0ull;
    while (true) {
        int ni = i, nchn = ch + 1;
        TD nxt; bool have = true;
        if (nchn >= cur.nch) {
            ni = i + gridDim.x; nchn = 0;
            have = (ni < ntask);
            if (have) nxt = dec_task(phase, ni, c);
        } else nxt = cur;
        if (have) {
            issue_chunk(nxt, nchn, AsB[b ^ 1], WsB[b ^ 1], tid);
            asm volatile("cp.async.wait_group 1;" ::: "memory");
        } else {
            asm volatile("cp.async.wait_group 0;" ::: "memory");
        }
        __syncthreads();
        compute64<68>(AsB[b], WsB[b], acc, bg, cg);
        if (ch == cur.nch - 1) {
#pragma unroll
            for (int x = 0; x < 4; x++) {
                float* o = cur.outp + (size_t)(bg + 8 * x) * cur.out_ld + cur.cbase;
#pragma unroll
                for (int y = 0; y < 8; y++) {
                    float2 p = up2(acc[x][y]);
                    o[cg + 16 * y] = p.x + p.y;
                    acc[x][y] = 0ull;
                }
            }
        }
        __syncthreads();   // protect buffer reuse across warps
        if (!have) break;
        i = ni; ch = nchn; cur = nxt; b ^= 1;
    }
}

// ---------------- GRU gates + state update (R9 verbatim, stride-generic) --------
__device__ __forceinline__ void gru_gates(const float* gi_pre, int nx,
                                          const float* bih, int nh,
                                          const float* bhh,
                                          float* h, float* ys, int nblk) {
    for (int idx = blockIdx.x * 128 + threadIdx.x; idx < Bsz * Hsz; idx += nblk * 128) {
        int b = idx >> 10, j = idx & 1023;
        float ir, iz, in_;
        if (gi_pre) {
            const float* g = gi_pre + (size_t)b * G3H;
            ir = g[j]; iz = g[Hsz + j]; in_ = g[2 * Hsz + j];
        } else {
            ir = bih[j]; iz = bih[Hsz + j]; in_ = bih[2 * Hsz + j];
            for (int s = 0; s < nx; s++) {
                const float* p = g_px + (size_t)s * Bsz * G3H + (size_t)b * G3H;
                ir += p[j]; iz += p[Hsz + j]; in_ += p[2 * Hsz + j];
            }
        }
        float hr = bhh[j], hz = bhh[Hsz + j], hn = bhh[2 * Hsz + j];
        for (int s = 0; s < nh; s++) {
            const float* p = g_ph + (size_t)s * Bsz * G3H + (size_t)b * G3H;
            hr += p[j]; hz += p[Hsz + j]; hn += p[2 * Hsz + j];
        }
        float r = 1.f / (1.f + expf(-(ir + hr)));
        float z = 1.f / (1.f + expf(-(iz + hz)));
        float n = tanhf(in_ + r * hn);
        float hv = h[idx];
        float hnew = (1.f - z) * n + z * hv;
        h[idx] = hnew;
        if (ys) ys[idx] = hnew;
    }
}

// ---------------- small kernels ----------------
__global__ void k_init(const int* __restrict__ trg) {
    int i = blockIdx.x * blockDim.x + threadIdx.x;
    if (i < Bsz * Hsz) { g_h1[i] = 0.f; g_h2[i] = 0.f; }
    if (i < Bsz) { g_tok[i] = trg[i * Tsz]; g_amax[i] = 0ull; }
}

__global__ void k_zero0(float* __restrict__ out) {
    int i = blockIdx.x * blockDim.x + threadIdx.x;
    if (i < Bsz * Vsz) {
        int b = i / Vsz, v = i - b * Vsz;
        out[(size_t)b * ((size_t)Tsz * Vsz) + v] = 0.f;
    }
}

// bulk input-gate GEMM (R9 verbatim)
__global__ void __launch_bounds__(128, 3) k_big(
    const float* __restrict__ emb, const int* __restrict__ src,
    const float* __restrict__ W, const float* __restrict__ bias,
    int K, int gather)
{
    __shared__ float As[32][68];
    __shared__ float Ws[128][66];
    __shared__ int s_tok[32];
    int tid = threadIdx.x, tblk = blockIdx.y, cbase = blockIdx.x * 128;
    const float* A; int lda; const int* tp = nullptr;
    if (gather) {
        if (tid < 32) s_tok[tid] = src[tid * Ssz + tblk];
        __syncthreads();
        tp = s_tok; A = emb; lda = Esz;
    } else {
        A = g_ys0 + (size_t)tblk * Bsz * Hsz; lda = Hsz;
    }
    gemm_task(A, tp, lda, W, K, 0, K / 64, cbase,
              g_gi + (size_t)tblk * Bsz * G3H, G3H, bias, As, Ws);
}

// persistent encoder layer (R9 verbatim)
__global__ void __launch_bounds__(128, 3) k_enc(
    const float* __restrict__ U, const float* __restrict__ bhh, int layer)
{
    __shared__ float As[32][68];
    __shared__ float Ws[128][66];
    int bid = blockIdx.x;
    float* h = layer ? g_h2 : g_h1;
    for (int t = 0; t < Ssz; t++) {
        for (int task = bid; task < 384; task += NBLK_ENC) {
            int ct = task % 24, s = task / 24;
            gemm_task(h, nullptr, Hsz, U, Hsz, s * 64, 1, ct * 128,
                      g_ph + (size_t)s * Bsz * G3H, G3H, nullptr, As, Ws);
        }
        gbar();
        gru_gates(g_gi + (size_t)t * Bsz * G3H, 0, nullptr, 16, bhh,
                  h, layer ? nullptr : (g_ys0 + (size_t)t * Bsz * Hsz), NBLK_ENC);
        gbar();
    }
}

// persistent decoder with pipelined phases
__global__ void __launch_bounds__(128, 2) k_dec(
    const float* __restrict__ demb,
    const float* __restrict__ dW0, const float* __restrict__ dU0,
    const float* __restrict__ dbi0, const float* __restrict__ dbh0,
    const float* __restrict__ dW1, const float* __restrict__ dU1,
    const float* __restrict__ dbi1, const float* __restrict__ dbh1,
    const float* __restrict__ fcW, const float* __restrict__ fcb,
    float* __restrict__ out)
{
    extern __shared__ float dyn[];
    float (*AsB)[32][68] = (float(*)[32][68])dyn;                  // 2 x 8704 B
    float (*WsB)[128][68] = (float(*)[128][68])(dyn + 2 * 32 * 68); // 2 x 34816 B
    __shared__ int s_tok[32];
    __shared__ ull sk[32];
    int tid = threadIdx.x, bid = blockIdx.x;
    DecCtx ctx = {demb, dW0, dU0, dW1, dU1, fcW, s_tok};

    for (int step = 0; step < Tsz - 1; step++) {
        if (tid < 32)
            s_tok[tid] = (step == 0)
                ? g_tok[tid]
                : (int)(0xFFFFFFFFu - (unsigned)(g_amax[tid] & 0xFFFFFFFFull));
        __syncthreads();
        run_phase(0, 576, ctx, AsB, WsB);                          // P1
        gbar();
        gru_gates(nullptr, 8, dbi0, 16, dbh0, g_h1, nullptr, NBLK_DEC);  // P2
        if (bid == 0 && tid < 32) g_amax[tid] = 0ull;
        gbar();
        run_phase(1, 768, ctx, AsB, WsB);                          // P3
        gbar();
        gru_gates(nullptr, 16, dbi1, 16, dbh1, g_h2, nullptr, NBLK_DEC); // P4
        gbar();
        run_phase(2, 2000, ctx, AsB, WsB);                         // P5 (FC)
        gbar();
        // P6: reduce partials + bias, store logits, deterministic argmax
        if (tid < 32) sk[tid] = 0ull;
        __syncthreads();
        for (int unit = bid * 128 + tid; unit < Bsz * (Vsz / 4); unit += NBLK_DEC * 128) {
            int row = unit / (Vsz / 4), c4 = unit - row * (Vsz / 4);
            int c = c4 * 4;
            float4 sacc = *(const float4*)&fcb[c];
            for (int s = 0; s < 8; s++) {
                const float4 p = *(const float4*)&g_pfc[(size_t)s * Bsz * Vsz +
                                                        (size_t)row * Vsz + c];
                sacc.x += p.x; sacc.y += p.y; sacc.z += p.z; sacc.w += p.w;
            }
            *(float4*)&out[(size_t)row * ((size_t)Tsz * Vsz) +
                           (size_t)(step + 1) * Vsz + c] = sacc;
            float bv = sacc.x; int bc = c;
            if (sacc.y > bv) { bv = sacc.y; bc = c + 1; }
            if (sacc.z > bv) { bv = sacc.z; bc = c + 2; }
            if (sacc.w > bv) { bv = sacc.w; bc = c + 3; }
            atomicMax(&sk[row], packkey(bv, bc));
        }
        __syncthreads();
        if (tid < 32 && sk[tid]) atomicMax(&g_amax[tid], sk[tid]);
        gbar();
    }
}

extern "C" void kernel_launch(void* const* d_in, const int* in_sizes, int n_in,
                              void* d_out, int out_size) {
    const int* src = (const int*)d_in[0];
    const int* trg = (const int*)d_in[1];
    const float* enc_emb = (const float*)d_in[3];
    const float* eW0 = (const float*)d_in[4];
    const float* eU0 = (const float*)d_in[5];
    const float* ebi0 = (const float*)d_in[6];
    const float* ebh0 = (const float*)d_in[7];
    const float* eW1 = (const float*)d_in[8];
    const float* eU1 = (const float*)d_in[9];
    const float* ebi1 = (const float*)d_in[10];
    const float* ebh1 = (const float*)d_in[11];
    const float* demb = (const float*)d_in[12];
    const float* dW0 = (const float*)d_in[13];
    const float* dU0 = (const float*)d_in[14];
    const float* dbi0 = (const float*)d_in[15];
    const float* dbh0 = (const float*)d_in[16];
    const float* dW1 = (const float*)d_in[17];
    const float* dU1 = (const float*)d_in[18];
    const float* dbi1 = (const float*)d_in[19];
    const float* dbh1 = (const float*)d_in[20];
    const float* fcW = (const float*)d_in[21];
    const float* fcb = (const float*)d_in[22];
    float* out = (float*)d_out;

    const int DYN = (2 * 32 * 68 + 2 * 128 * 68) * 4;   // 87040 B
    cudaFuncSetAttribute(k_dec, cudaFuncAttributeMaxDynamicSharedMemorySize, DYN);

    k_init<<<128, 256>>>(trg);
    k_zero0<<<(Bsz * Vsz + 255) / 256, 256>>>(out);

    k_big<<<dim3(24, 128), 128>>>(enc_emb, src, eW0, ebi0, Esz, 1);
    k_enc<<<NBLK_ENC, 128>>>(eU0, ebh0, 0);
    k_big<<<dim3(24, 128), 128>>>(nullptr, nullptr, eW1, ebi1, Hsz, 0);
    k_enc<<<NBLK_ENC, 128>>>(eU1, ebh1, 1);
    k_dec<<<NBLK_DEC, 128, DYN>>>(demb, dW0, dU0, dbi0, dbh0,
                                  dW1, dU1, dbi1, dbh1, fcW, fcb, out);
}

// round 13
// speedup vs baseline: 1.5581x; 1.0106x over previous
#include <cuda_runtime.h>
#include <math.h>

typedef unsigned long long ull;

#define Bsz 32
#define Ssz 128
#define Tsz 128
#define Hsz 1024
#define G3H 3072
#define Esz 512
#define Vsz 32000
#define NBLK_ENC 444
#define NBLK_DEC 296
#define NBUCKET 37

// ---------------- static scratch ----------------
__device__ float g_gi[(size_t)Ssz * Bsz * G3H];
__device__ float g_ys0[(size_t)Ssz * Bsz * Hsz];
__device__ float g_px[(size_t)16 * Bsz * G3H];
__device__ float g_ph[(size_t)16 * Bsz * G3H];
__device__ float g_h1[Bsz * Hsz];
__device__ float g_h2[Bsz * Hsz];
__device__ int g_tok[Bsz];
__device__ ull g_amax[Bsz];
__device__ unsigned g_bar_c1[NBUCKET * 32];
__device__ unsigned g_bar_c2;
__device__ unsigned g_bar_gen;

// ---------------- helpers ----------------
__device__ __forceinline__ ull ffma2(ull a, ull b, ull c) {
    ull d;
    asm("fma.rn.f32x2 %0, %1, %2, %3;" : "=l"(d) : "l"(a), "l"(b), "l"(c));
    return d;
}
__device__ __forceinline__ float2 up2(ull v) {
    float2 f;
    asm("mov.b64 {%0, %1}, %2;" : "=f"(f.x), "=f"(f.y) : "l"(v));
    return f;
}
__device__ __forceinline__ ull packkey(float v, int c) {
    unsigned b = __float_as_uint(v);
    b = (b & 0x80000000u) ? ~b : (b | 0x80000000u);
    return ((ull)b << 32) | (ull)(0xFFFFFFFFu - (unsigned)c);
}
__device__ __forceinline__ void cp16(void* dst, const void* src) {
    unsigned s = (unsigned)__cvta_generic_to_shared(dst);
    asm volatile("cp.async.cg.shared.global [%0], [%1], 16;" :: "r"(s), "l"(src));
}

// grid barrier: 2-level buckets, SELF-RESETTING counters (atomicExch back to 0
// by the last arrival) -> immune to mixed grid sizes and graph replays.
// Release chain fence-complete; gen monotonic.
__device__ __forceinline__ void gbar() {
    __syncthreads();
    __threadfence();
    if (threadIdx.x == 0) {
        unsigned gen;
        asm volatile("ld.acquire.gpu.u32 %0, [%1];"
                     : "=r"(gen) : "l"(&g_bar_gen) : "memory");
        unsigned bsz = gridDim.x / NBUCKET;
        unsigned b = blockIdx.x % NBUCKET;
        bool master = false;
        if (atomicAdd(&g_bar_c1[b * 32], 1u) == bsz - 1u) {
            atomicExch(&g_bar_c1[b * 32], 0u);   // all bsz arrivals in; safe reset
            __threadfence();                      // bucket data -> c2 chain
            if (atomicAdd(&g_bar_c2, 1u) == NBUCKET - 1u) {
                atomicExch(&g_bar_c2, 0u);
                master = true;
            }
        }
        if (master) {
            __threadfence();
            asm volatile("st.release.gpu.u32 [%0], %1;"
                         :: "l"(&g_bar_gen), "r"(gen + 1u) : "memory");
        } else {
            unsigned cur;
            while (true) {
                asm volatile("ld.acquire.gpu.u32 %0, [%1];"
                             : "=r"(cur) : "l"(&g_bar_gen) : "memory");
                if (cur != gen) break;
                __nanosleep(32);
            }
        }
    }
    __syncthreads();
    __threadfence();
}

// ---------------- frozen inner compute: 64-k chunk, K-parity FFMA2 ----------------
template <int LDW>
__device__ __forceinline__ void compute64(const float (*As)[68], const float (*Ws)[LDW],
                                          ull acc[4][8], int bg, int cg) {
#pragma unroll 4
    for (int g = 0; g < 16; g++) {
        const int k0 = g * 4;
        ull a0l = *(const ull*)&As[bg][k0],      a0h = *(const ull*)&As[bg][k0 + 2];
        ull a1l = *(const ull*)&As[bg + 8][k0],  a1h = *(const ull*)&As[bg + 8][k0 + 2];
        ull a2l = *(const ull*)&As[bg + 16][k0], a2h = *(const ull*)&As[bg + 16][k0 + 2];
        ull a3l = *(const ull*)&As[bg + 24][k0], a3h = *(const ull*)&As[bg + 24][k0 + 2];
#pragma unroll
        for (int j = 0; j < 8; j++) {
            ull w0 = *(const ull*)&Ws[cg + 16 * j][k0];
            ull w1 = *(const ull*)&Ws[cg + 16 * j][k0 + 2];
            acc[0][j] = ffma2(a0l, w0, acc[0][j]);
            acc[1][j] = ffma2(a1l, w0, acc[1][j]);
            acc[2][j] = ffma2(a2l, w0, acc[2][j]);
            acc[3][j] = ffma2(a3l, w0, acc[3][j]);
            acc[0][j] = ffma2(a0h, w1, acc[0][j]);
            acc[1][j] = ffma2(a1h, w1, acc[1][j]);
            acc[2][j] = ffma2(a2h, w1, acc[2][j]);
            acc[3][j] = ffma2(a3h, w1, acc[3][j]);
        }
    }
}

// ---------------- synchronous GEMM task (k_big path) ----------------
__device__ __noinline__ void gemm_task(
    const float* __restrict__ A, const int* __restrict__ toks, int lda,
    const float* __restrict__ W, int ldw,
    int kbase, int nchunk, int cbase,
    float* __restrict__ outp, int out_ld, const float* __restrict__ bias,
    float (*As)[68], float (*Ws)[66])
{
    const int tid = threadIdx.x;
    const int bg = tid >> 4, cg = tid & 15;
    ull acc[4][8];
#pragma unroll
    for (int i = 0; i < 4; i++)
#pragma unroll
        for (int j = 0; j < 8; j++) acc[i][j] = 0ull;

    for (int ch = 0; ch < nchunk; ch++) {
        const int kb = kbase + ch * 64;
        __syncthreads();
#pragma unroll
        for (int r = 0; r < 4; r++) {
            int f4 = tid + r * 128, row = f4 >> 4, kq = f4 & 15;
            const float* src = toks ? (A + (size_t)toks[row] * lda)
                                    : (A + (size_t)row * lda);
            float4 v = *(const float4*)(src + kb + kq * 4);
            *(float4*)&As[row][kq * 4] = v;
        }
#pragma unroll 4
        for (int r = 0; r < 16; r++) {
            int f4 = tid + r * 128, c = f4 >> 4, kq = f4 & 15;
            float4 v = *(const float4*)(W + (size_t)(cbase + c) * ldw + kb + kq * 4);
            *(float2*)&Ws[c][kq * 4] = make_float2(v.x, v.y);
            *(float2*)&Ws[c][kq * 4 + 2] = make_float2(v.z, v.w);
        }
        __syncthreads();
        compute64<66>(As, Ws, acc, bg, cg);
    }
#pragma unroll
    for (int i = 0; i < 4; i++) {
        float* o = outp + (size_t)(bg + 8 * i) * out_ld + cbase;
#pragma unroll
        for (int j = 0; j < 8; j++) {
            float2 p = up2(acc[i][j]);
            float v = p.x + p.y;
            int c = cg + 16 * j;
            if (bias) v += bias[cbase + c];
            o[c] = v;
        }
    }
}

// ---------------- pipelined decoder phase executor (R10 verbatim) ----------------
struct TD {
    const float* A; const int* toks; const float* W; float* outp;
    int lda, ldw, kbase, nch, cbase, out_ld;
};

struct DecCtx {
    const float *demb, *dW0, *dU0, *dW1, *dU1, *fcW;
    const int* stok;
};

__device__ __forceinline__ TD dec_task(int phase, int t, const DecCtx& c) {
    TD d;
    if (phase == 0) {               // P1: 576 tasks
        if (t < 192) {
            int ct = t % 24, s = t / 24;                     // gi: 8 slices of 64
            d = {c.demb, c.stok, c.dW0, g_px + (size_t)s * Bsz * G3H,
                 Esz, Esz, s * 64, 1, ct * 128, G3H};
        } else {
            int t2 = t - 192, ct = t2 % 24, s = t2 / 24;     // gh: 16 slices of 64
            d = {g_h1, nullptr, c.dU0, g_ph + (size_t)s * Bsz * G3H,
                 Hsz, Hsz, s * 64, 1, ct * 128, G3H};
        }
    } else {                        // P3: 768 tasks
        if (t < 384) {
            int ct = t % 24, s = t / 24;
            d = {g_h1, nullptr, c.dW1, g_px + (size_t)s * Bsz * G3H,
                 Hsz, Hsz, s * 64, 1, ct * 128, G3H};
        } else {
            int t2 = t - 384, ct = t2 % 24, s = t2 / 24;
            d = {g_h2, nullptr, c.dU1, g_ph + (size_t)s * Bsz * G3H,
                 Hsz, Hsz, s * 64, 1, ct * 128, G3H};
        }
    }
    return d;
}

__device__ __forceinline__ void issue_chunk(const TD& t, int ch,
                                            float (*As)[68], float (*Ws)[68], int tid) {
    const int kb = t.kbase + ch * 64;
#pragma unroll
    for (int r = 0; r < 4; r++) {
        int f4 = tid + r * 128, row = f4 >> 4, kq = f4 & 15;
        const float* src = t.toks ? (t.A + (size_t)t.toks[row] * t.lda)
                                  : (t.A + (size_t)row * t.lda);
        cp16(&As[row][kq * 4], src + kb + kq * 4);
    }
#pragma unroll 4
    for (int r = 0; r < 16; r++) {
        int f4 = tid + r * 128, c = f4 >> 4, kq = f4 & 15;
        cp16(&Ws[c][kq * 4], t.W + (size_t)(t.cbase + c) * t.ldw + kb + kq * 4);
    }
    asm volatile("cp.async.commit_group;" ::: "memory");
}

__device__ __noinline__ void run_phase(int phase, int ntask, const DecCtx& c,
                                       float (*AsB)[32][68], float (*WsB)[128][68]) {
    const int tid = threadIdx.x;
    const int bg = tid >> 4, cg = tid & 15;
    int i = blockIdx.x;
    if (i >= ntask) return;
    TD cur = dec_task(phase, i, c);
    int ch = 0, b = 0;
    issue_chunk(cur, 0, AsB[0], WsB[0], tid);
    ull acc[4][8];
#pragma unroll
    for (int x = 0; x < 4; x++)
#pragma unroll
        for (int y = 0; y < 8; y++) acc[x][y] = 0ull;
    while (true) {
        int ni = i, nchn = ch + 1;
        TD nxt; bool have = true;
        if (nchn >= cur.nch) {
            ni = i + gridDim.x; nchn = 0;
            have = (ni < ntask);
            if (have) nxt = dec_task(phase, ni, c);
        } else nxt = cur;
        if (have) {
            issue_chunk(nxt, nchn, AsB[b ^ 1], WsB[b ^ 1], tid);
            asm volatile("cp.async.wait_group 1;" ::: "memory");
        } else {
            asm volatile("cp.async.wait_group 0;" ::: "memory");
        }
        __syncthreads();
        compute64<68>(AsB[b], WsB[b], acc, bg, cg);
        if (ch == cur.nch - 1) {
#pragma unroll
            for (int x = 0; x < 4; x++) {
                float* o = cur.outp + (size_t)(bg + 8 * x) * cur.out_ld + cur.cbase;
#pragma unroll
                for (int y = 0; y < 8; y++) {
                    float2 p = up2(acc[x][y]);
                    o[cg + 16 * y] = p.x + p.y;
                    acc[x][y] = 0ull;
                }
            }
        }
        __syncthreads();
        if (!have) break;
        i = ni; ch = nchn; cur = nxt; b ^= 1;
    }
}

// ---------------- fused FC: bit-exact vs R10's P5+P6 chain ----------------
__device__ __noinline__ void run_fc(const float* __restrict__ fcW,
                                    const float* __restrict__ fcb,
                                    float* __restrict__ out, int step,
                                    float (*AsB)[32][68], float (*WsB)[128][68],
                                    ull* sk) {
    const int tid = threadIdx.x, bid = blockIdx.x;
    if (bid >= 250) return;
    const int bg = tid >> 4, cg = tid & 15;
    const int cbase = bid * 128;
    if (tid < 32) sk[tid] = 0ull;
    float rsum[4][8];
#pragma unroll
    for (int x = 0; x < 4; x++)
#pragma unroll
        for (int y = 0; y < 8; y++) rsum[x][y] = fcb[cbase + cg + 16 * y];

    TD fc;
    fc.A = g_h2; fc.toks = nullptr; fc.W = fcW; fc.outp = nullptr;
    fc.lda = Hsz; fc.ldw = Hsz; fc.kbase = 0; fc.nch = 16;
    fc.cbase = cbase; fc.out_ld = 0;

    issue_chunk(fc, 0, AsB[0], WsB[0], tid);
    int b = 0;
    ull acc[4][8];
#pragma unroll
    for (int x = 0; x < 4; x++)
#pragma unroll
        for (int y = 0; y < 8; y++) acc[x][y] = 0ull;
    for (int u = 0; u < 16; u++) {          // chunk u = K-slice u/2, half u&1
        if (u + 1 < 16) {
            issue_chunk(fc, u + 1, AsB[b ^ 1], WsB[b ^ 1], tid);
            asm volatile("cp.async.wait_group 1;" ::: "memory");
        } else {
            asm volatile("cp.async.wait_group 0;" ::: "memory");
        }
        __syncthreads();
        compute64<68>(AsB[b], WsB[b], acc, bg, cg);
        if (u & 1) {                        // slice boundary: fold (p.x+p.y), reset
#pragma unroll
            for (int x = 0; x < 4; x++)
#pragma unroll
                for (int y = 0; y < 8; y++) {
                    float2 p = up2(acc[x][y]);
                    rsum[x][y] += p.x + p.y;
                    acc[x][y] = 0ull;
                }
        }
        __syncthreads();
        b ^= 1;
    }
#pragma unroll
    for (int x = 0; x < 4; x++) {
        int row = bg + 8 * x;
        float* o = out + (size_t)row * ((size_t)Tsz * Vsz)
                 + (size_t)(step + 1) * Vsz + cbase;
        float bv = -3.4e38f; int bc = 0;
#pragma unroll
        for (int y = 0; y < 8; y++) {
            int c = cg + 16 * y;
            o[c] = rsum[x][y];
            if (rsum[x][y] > bv) { bv = rsum[x][y]; bc = cbase + c; }
        }
        atomicMax(&sk[row], packkey(bv, bc));
    }
    __syncthreads();
    if (tid < 32) atomicMax(&g_amax[tid], sk[tid]);
}

// ---------------- GRU gates + state update (frozen sum order) ----------------
__device__ __forceinline__ void gru_gates(const float* gi_pre, int nx,
                                          const float* bih, int nh,
                                          const float* bhh,
                                          float* h, float* ys, int nblk) {
    for (int idx = blockIdx.x * 128 + threadIdx.x; idx < Bsz * Hsz; idx += nblk * 128) {
        int b = idx >> 10, j = idx & 1023;
        float ir, iz, in_;
        if (gi_pre) {
            const float* g = gi_pre + (size_t)b * G3H;
            ir = g[j]; iz = g[Hsz + j]; in_ = g[2 * Hsz + j];
        } else {
            ir = bih[j]; iz = bih[Hsz + j]; in_ = bih[2 * Hsz + j];
            for (int s = 0; s < nx; s++) {
                const float* p = g_px + (size_t)s * Bsz * G3H + (size_t)b * G3H;
                ir += p[j]; iz += p[Hsz + j]; in_ += p[2 * Hsz + j];
            }
        }
        float hr = bhh[j], hz = bhh[Hsz + j], hn = bhh[2 * Hsz + j];
        for (int s = 0; s < nh; s++) {
            const float* p = g_ph + (size_t)s * Bsz * G3H + (size_t)b * G3H;
            hr += p[j]; hz += p[Hsz + j]; hn += p[2 * Hsz + j];
        }
        float r = 1.f / (1.f + expf(-(ir + hr)));
        float z = 1.f / (1.f + expf(-(iz + hz)));
        float n = tanhf(in_ + r * hn);
        float hv = h[idx];
        float hnew = (1.f - z) * n + z * hv;
        h[idx] = hnew;
        if (ys) ys[idx] = hnew;
    }
}

// ---------------- small kernels ----------------
__global__ void k_init(const int* __restrict__ trg) {
    int i = blockIdx.x * blockDim.x + threadIdx.x;
    if (i < Bsz * Hsz) { g_h1[i] = 0.f; g_h2[i] = 0.f; }
    if (i < Bsz) { g_tok[i] = trg[i * Tsz]; g_amax[i] = 0ull; }
}

__global__ void k_zero0(float* __restrict__ out) {
    int i = blockIdx.x * blockDim.x + threadIdx.x;
    if (i < Bsz * Vsz) {
        int b = i / Vsz, v = i - b * Vsz;
        out[(size_t)b * ((size_t)Tsz * Vsz) + v] = 0.f;
    }
}

// bulk input-gate GEMM (verbatim)
__global__ void __launch_bounds__(128, 3) k_big(
    const float* __restrict__ emb, const int* __restrict__ src,
    const float* __restrict__ W, const float* __restrict__ bias,
    int K, int gather)
{
    __shared__ float As[32][68];
    __shared__ float Ws[128][66];
    __shared__ int s_tok[32];
    int tid = threadIdx.x, tblk = blockIdx.y, cbase = blockIdx.x * 128;
    const float* A; int lda; const int* tp = nullptr;
    if (gather) {
        if (tid < 32) s_tok[tid] = src[tid * Ssz + tblk];
        __syncthreads();
        tp = s_tok; A = emb; lda = Esz;
    } else {
        A = g_ys0 + (size_t)tblk * Bsz * Hsz; lda = Hsz;
    }
    gemm_task(A, tp, lda, W, K, 0, K / 64, cbase,
              g_gi + (size_t)tblk * Bsz * G3H, G3H, bias, As, Ws);
}

// persistent encoder layer: W tile pinned in smem across all 128 steps.
// Same task map, slice widths, and summation order as R10's k_enc.
__global__ void __launch_bounds__(128, 3) k_enc(
    const float* __restrict__ U, const float* __restrict__ bhh, int layer)
{
    __shared__ float As[32][68];
    __shared__ float Ws[128][66];
    const int tid = threadIdx.x, bid = blockIdx.x;
    const int bg = tid >> 4, cg = tid & 15;
    const bool active = bid < 384;
    const int ct = bid % 24, s = bid / 24;
    const int cbase = ct * 128, kb = s * 64;
    float* h = layer ? g_h2 : g_h1;
    if (active) {
#pragma unroll 4
        for (int r = 0; r < 16; r++) {
            int f4 = tid + r * 128, c = f4 >> 4, kq = f4 & 15;
            float4 v = *(const float4*)(U + (size_t)(cbase + c) * Hsz + kb + kq * 4);
            *(float2*)&Ws[c][kq * 4] = make_float2(v.x, v.y);
            *(float2*)&Ws[c][kq * 4 + 2] = make_float2(v.z, v.w);
        }
    }
    for (int t = 0; t < Ssz; t++) {
        if (active) {
            __syncthreads();
#pragma unroll
            for (int r = 0; r < 4; r++) {
                int f4 = tid + r * 128, row = f4 >> 4, kq = f4 & 15;
                float4 v = *(const float4*)(h + (size_t)row * Hsz + kb + kq * 4);
                *(float4*)&As[row][kq * 4] = v;
            }
            __syncthreads();
            ull acc[4][8];
#pragma unroll
            for (int i = 0; i < 4; i++)
#pragma unroll
                for (int j = 0; j < 8; j++) acc[i][j] = 0ull;
            compute64<66>(As, Ws, acc, bg, cg);
            float* outp = g_ph + (size_t)s * Bsz * G3H;
#pragma unroll
            for (int i = 0; i < 4; i++) {
                float* o = outp + (size_t)(bg + 8 * i) * G3H + cbase;
#pragma unroll
                for (int j = 0; j < 8; j++) {
                    float2 p = up2(acc[i][j]);
                    o[cg + 16 * j] = p.x + p.y;
                }
            }
        }
        gbar();
        gru_gates(g_gi + (size_t)t * Bsz * G3H, 0, nullptr, 16, bhh,
                  h, layer ? nullptr : (g_ys0 + (size_t)t * Bsz * Hsz), NBLK_ENC);
        gbar();
    }
}

// persistent decoder: R10 phase structure with P5+P6 replaced by fused run_fc
__global__ void __launch_bounds__(128, 2) k_dec(
    const float* __restrict__ demb,
    const float* __restrict__ dW0, const float* __restrict__ dU0,
    const float* __restrict__ dbi0, const float* __restrict__ dbh0,
    const float* __restrict__ dW1, const float* __restrict__ dU1,
    const float* __restrict__ dbi1, const float* __restrict__ dbh1,
    const float* __restrict__ fcW, const float* __restrict__ fcb,
    float* __restrict__ out)
{
    extern __shared__ float dyn[];
    float (*AsB)[32][68] = (float(*)[32][68])dyn;
    float (*WsB)[128][68] = (float(*)[128][68])(dyn + 2 * 32 * 68);
    __shared__ int s_tok[32];
    __shared__ ull sk[32];
    int tid = threadIdx.x, bid = blockIdx.x;
    DecCtx ctx = {demb, dW0, dU0, dW1, dU1, fcW, s_tok};

    for (int step = 0; step < Tsz - 1; step++) {
        if (tid < 32)
            s_tok[tid] = (step == 0)
                ? g_tok[tid]
                : (int)(0xFFFFFFFFu - (unsigned)(g_amax[tid] & 0xFFFFFFFFull));
        __syncthreads();
        run_phase(0, 576, ctx, AsB, WsB);                                 // P1
        gbar();
        gru_gates(nullptr, 8, dbi0, 16, dbh0, g_h1, nullptr, NBLK_DEC);   // P2
        if (bid == 0 && tid < 32) g_amax[tid] = 0ull;
        gbar();
        run_phase(1, 768, ctx, AsB, WsB);                                 // P3
        gbar();
        gru_gates(nullptr, 16, dbi1, 16, dbh1, g_h2, nullptr, NBLK_DEC);  // P4
        gbar();
        run_fc(fcW, fcb, out, step, AsB, WsB, sk);                        // P5'
        gbar();
    }
}

extern "C" void kernel_launch(void* const* d_in, const int* in_sizes, int n_in,
                              void* d_out, int out_size) {
    const int* src = (const int*)d_in[0];
    const int* trg = (const int*)d_in[1];
    const float* enc_emb = (const float*)d_in[3];
    const float* eW0 = (const float*)d_in[4];
    const float* eU0 = (const float*)d_in[5];
    const float* ebi0 = (const float*)d_in[6];
    const float* ebh0 = (const float*)d_in[7];
    const float* eW1 = (const float*)d_in[8];
    const float* eU1 = (const float*)d_in[9];
    const float* ebi1 = (const float*)d_in[10];
    const float* ebh1 = (const float*)d_in[11];
    const float* demb = (const float*)d_in[12];
    const float* dW0 = (const float*)d_in[13];
    const float* dU0 = (const float*)d_in[14];
    const float* dbi0 = (const float*)d_in[15];
    const float* dbh0 = (const float*)d_in[16];
    const float* dW1 = (const float*)d_in[17];
    const float* dU1 = (const float*)d_in[18];
    const float* dbi1 = (const float*)d_in[19];
    const float* dbh1 = (const float*)d_in[20];
    const float* fcW = (const float*)d_in[21];
    const float* fcb = (const float*)d_in[22];
    float* out = (float*)d_out;

    const int DYN = (2 * 32 * 68 + 2 * 128 * 68) * 4;   // 87040 B
    cudaFuncSetAttribute(k_dec, cudaFuncAttributeMaxDynamicSharedMemorySize, DYN);

    k_init<<<128, 256>>>(trg);
    k_zero0<<<(Bsz * Vsz + 255) / 256, 256>>>(out);

    k_big<<<dim3(24, 128), 128>>>(enc_emb, src, eW0, ebi0, Esz, 1);
    k_enc<<<NBLK_ENC, 128>>>(eU0, ebh0, 0);
    k_big<<<dim3(24, 128), 128>>>(nullptr, nullptr, eW1, ebi1, Hsz, 0);
    k_enc<<<NBLK_ENC, 128>>>(eU1, ebh1, 1);
    k_dec<<<NBLK_DEC, 128, DYN>>>(demb, dW0, dU0, dbi0, dbh0,
                                  dW1, dU1, dbi1, dbh1, fcW, fcb, out);
}

// round 14
// speedup vs baseline: 1.6713x; 1.0726x over previous
#include <cuda_runtime.h>
#include <math.h>

typedef unsigned long long ull;

#define Bsz 32
#define Ssz 128
#define Tsz 128
#define Hsz 1024
#define G3H 3072
#define Esz 512
#define Vsz 32000
#define NBLK_ENC 444
#define NBLK_DEC 296
#define NBUCKET 37

// ---------------- static scratch ----------------
__device__ float g_gi[(size_t)Ssz * Bsz * G3H];
__device__ float g_ys0[(size_t)Ssz * Bsz * Hsz];
__device__ float g_px[(size_t)16 * Bsz * G3H];
__device__ float g_ph[(size_t)16 * Bsz * G3H];    // L0 h-partials
__device__ float g_ph1[(size_t)16 * Bsz * G3H];   // L1 h-partials
__device__ float g_h1[Bsz * Hsz];
__device__ float g_h2[Bsz * Hsz];
__device__ int g_tok[Bsz];
__device__ ull g_amax[Bsz];
__device__ unsigned g_bar_c1[NBUCKET * 32];
__device__ unsigned g_bar_c2;
__device__ unsigned g_bar_gen;

// ---------------- helpers ----------------
__device__ __forceinline__ ull ffma2(ull a, ull b, ull c) {
    ull d;
    asm("fma.rn.f32x2 %0, %1, %2, %3;" : "=l"(d) : "l"(a), "l"(b), "l"(c));
    return d;
}
__device__ __forceinline__ float2 up2(ull v) {
    float2 f;
    asm("mov.b64 {%0, %1}, %2;" : "=f"(f.x), "=f"(f.y) : "l"(v));
    return f;
}
__device__ __forceinline__ ull packkey(float v, int c) {
    unsigned b = __float_as_uint(v);
    b = (b & 0x80000000u) ? ~b : (b | 0x80000000u);
    return ((ull)b << 32) | (ull)(0xFFFFFFFFu - (unsigned)c);
}
__device__ __forceinline__ void cp16(void* dst, const void* src) {
    unsigned s = (unsigned)__cvta_generic_to_shared(dst);
    asm volatile("cp.async.cg.shared.global [%0], [%1], 16;" :: "r"(s), "l"(src));
}

// grid barrier: 2-level buckets, self-resetting counters, fence-complete.
__device__ __forceinline__ void gbar() {
    __syncthreads();
    __threadfence();
    if (threadIdx.x == 0) {
        unsigned gen;
        asm volatile("ld.acquire.gpu.u32 %0, [%1];"
                     : "=r"(gen) : "l"(&g_bar_gen) : "memory");
        unsigned bsz = gridDim.x / NBUCKET;
        unsigned b = blockIdx.x % NBUCKET;
        bool master = false;
        if (atomicAdd(&g_bar_c1[b * 32], 1u) == bsz - 1u) {
            atomicExch(&g_bar_c1[b * 32], 0u);
            __threadfence();
            if (atomicAdd(&g_bar_c2, 1u) == NBUCKET - 1u) {
                atomicExch(&g_bar_c2, 0u);
                master = true;
            }
        }
        if (master) {
            __threadfence();
            asm volatile("st.release.gpu.u32 [%0], %1;"
                         :: "l"(&g_bar_gen), "r"(gen + 1u) : "memory");
        } else {
            unsigned cur;
            while (true) {
                asm volatile("ld.acquire.gpu.u32 %0, [%1];"
                             : "=r"(cur) : "l"(&g_bar_gen) : "memory");
                if (cur != gen) break;
                __nanosleep(32);
            }
        }
    }
    __syncthreads();
    __threadfence();
}

// ---------------- frozen inner compute: 64-k chunk, K-parity FFMA2 ----------------
// LDS.128 loads (ulonglong2); values and FMA order bit-identical to R13.
__device__ __forceinline__ void compute64(const float (*As)[68], const float (*Ws)[68],
                                          ull acc[4][8], int bg, int cg) {
#pragma unroll 4
    for (int g = 0; g < 16; g++) {
        const int k0 = g * 4;
        ulonglong2 A0 = *(const ulonglong2*)&As[bg][k0];
        ulonglong2 A1 = *(const ulonglong2*)&As[bg + 8][k0];
        ulonglong2 A2 = *(const ulonglong2*)&As[bg + 16][k0];
        ulonglong2 A3 = *(const ulonglong2*)&As[bg + 24][k0];
#pragma unroll
        for (int j = 0; j < 8; j++) {
            ulonglong2 W01 = *(const ulonglong2*)&Ws[cg + 16 * j][k0];
            acc[0][j] = ffma2(A0.x, W01.x, acc[0][j]);
            acc[1][j] = ffma2(A1.x, W01.x, acc[1][j]);
            acc[2][j] = ffma2(A2.x, W01.x, acc[2][j]);
            acc[3][j] = ffma2(A3.x, W01.x, acc[3][j]);
            acc[0][j] = ffma2(A0.y, W01.y, acc[0][j]);
            acc[1][j] = ffma2(A1.y, W01.y, acc[1][j]);
            acc[2][j] = ffma2(A2.y, W01.y, acc[2][j]);
            acc[3][j] = ffma2(A3.y, W01.y, acc[3][j]);
        }
    }
}

// ---------------- synchronous GEMM task (k_big path) ----------------
__device__ __noinline__ void gemm_task(
    const float* __restrict__ A, const int* __restrict__ toks, int lda,
    const float* __restrict__ W, int ldw,
    int kbase, int nchunk, int cbase,
    float* __restrict__ outp, int out_ld, const float* __restrict__ bias,
    float (*As)[68], float (*Ws)[68])
{
    const int tid = threadIdx.x;
    const int bg = tid >> 4, cg = tid & 15;
    ull acc[4][8];
#pragma unroll
    for (int i = 0; i < 4; i++)
#pragma unroll
        for (int j = 0; j < 8; j++) acc[i][j] = 0ull;

    for (int ch = 0; ch < nchunk; ch++) {
        const int kb = kbase + ch * 64;
        __syncthreads();
#pragma unroll
        for (int r = 0; r < 4; r++) {
            int f4 = tid + r * 128, row = f4 >> 4, kq = f4 & 15;
            const float* src = toks ? (A + (size_t)toks[row] * lda)
                                    : (A + (size_t)row * lda);
            float4 v = *(const float4*)(src + kb + kq * 4);
            *(float4*)&As[row][kq * 4] = v;
        }
#pragma unroll 4
        for (int r = 0; r < 16; r++) {
            int f4 = tid + r * 128, c = f4 >> 4, kq = f4 & 15;
            float4 v = *(const float4*)(W + (size_t)(cbase + c) * ldw + kb + kq * 4);
            *(float4*)&Ws[c][kq * 4] = v;
        }
        __syncthreads();
        compute64(As, Ws, acc, bg, cg);
    }
#pragma unroll
    for (int i = 0; i < 4; i++) {
        float* o = outp + (size_t)(bg + 8 * i) * out_ld + cbase;
#pragma unroll
        for (int j = 0; j < 8; j++) {
            float2 p = up2(acc[i][j]);
            float v = p.x + p.y;
            int c = cg + 16 * j;
            if (bias) v += bias[cbase + c];
            o[c] = v;
        }
    }
}

// ---------------- decoder task descriptors ----------------
struct TD { const float* A; const int* toks; const float* W; float* outp;
            int ld, kbase, cbase; };

struct DecCtx {
    const float *demb, *dW0, *dU0, *dW1, *dU1;
    const int* stok;
};

// phase 0 task list: [0,192) gi (emb@dW0, 8 slices) -> g_px
//                    [192,576) ghL0 (h1@dU0, 16 slices) -> g_ph
//                    [576,960) ghL1 (h2@dU1, 16 slices) -> g_ph1
// phase 1 task list: [0,384) gi2 (h1@dW1, 16 slices) -> g_px
__device__ __forceinline__ TD dec_task(int phase, int t, const DecCtx& c) {
    TD d;
    if (phase == 0) {
        if (t < 192) {
            int ct = t % 24, s = t / 24;
            d = {c.demb, c.stok, c.dW0, g_px + (size_t)s * Bsz * G3H,
                 Esz, s * 64, ct * 128};
        } else if (t < 576) {
            int t2 = t - 192, ct = t2 % 24, s = t2 / 24;
            d = {g_h1, nullptr, c.dU0, g_ph + (size_t)s * Bsz * G3H,
                 Hsz, s * 64, ct * 128};
        } else {
            int t2 = t - 576, ct = t2 % 24, s = t2 / 24;
            d = {g_h2, nullptr, c.dU1, g_ph1 + (size_t)s * Bsz * G3H,
                 Hsz, s * 64, ct * 128};
        }
    } else {
        int ct = t % 24, s = t / 24;
        d = {g_h1, nullptr, c.dW1, g_px + (size_t)s * Bsz * G3H,
             Hsz, s * 64, ct * 128};
    }
    return d;
}

__device__ __forceinline__ void issue_tile(const float* A, const int* toks, int ld,
                                           const float* W, int kb, int cbase,
                                           float (*As)[68], float (*Ws)[68], int tid) {
#pragma unroll
    for (int r = 0; r < 4; r++) {
        int f4 = tid + r * 128, row = f4 >> 4, kq = f4 & 15;
        const float* src = toks ? (A + (size_t)toks[row] * ld)
                                : (A + (size_t)row * ld);
        cp16(&As[row][kq * 4], src + kb + kq * 4);
    }
#pragma unroll 4
    for (int r = 0; r < 16; r++) {
        int f4 = tid + r * 128, c = f4 >> 4, kq = f4 & 15;
        cp16(&Ws[c][kq * 4], W + (size_t)(cbase + c) * ld + kb + kq * 4);
    }
    asm volatile("cp.async.commit_group;" ::: "memory");
}

// pipelined 1-chunk task executor (task i0, i0+stride, ... < ntask)
__device__ __noinline__ void run_tasks(int phase, int i0, int ntask, int stride,
                                       const DecCtx& c,
                                       float (*AsB)[32][68], float (*WsB)[128][68]) {
    const int tid = threadIdx.x;
    const int bg = tid >> 4, cg = tid & 15;
    int i = i0;
    if (i >= ntask) return;
    TD cur = dec_task(phase, i, c);
    int b = 0;
    issue_tile(cur.A, cur.toks, cur.ld, cur.W, cur.kbase, cur.cbase,
               AsB[0], WsB[0], tid);
    while (true) {
        int ni = i + stride;
        bool have = (ni < ntask);
        TD nxt;
        if (have) {
            nxt = dec_task(phase, ni, c);
            issue_tile(nxt.A, nxt.toks, nxt.ld, nxt.W, nxt.kbase, nxt.cbase,
                       AsB[b ^ 1], WsB[b ^ 1], tid);
            asm volatile("cp.async.wait_group 1;" ::: "memory");
        } else {
            asm volatile("cp.async.wait_group 0;" ::: "memory");
        }
        __syncthreads();
        ull acc[4][8];
#pragma unroll
        for (int x = 0; x < 4; x++)
#pragma unroll
            for (int y = 0; y < 8; y++) acc[x][y] = 0ull;
        compute64(AsB[b], WsB[b], acc, bg, cg);
#pragma unroll
        for (int x = 0; x < 4; x++) {
            float* o = cur.outp + (size_t)(bg + 8 * x) * G3H + cur.cbase;
#pragma unroll
            for (int y = 0; y < 8; y++) {
                float2 p = up2(acc[x][y]);
                o[cg + 16 * y] = p.x + p.y;
            }
        }
        __syncthreads();
        if (!have) break;
        i = ni; cur = nxt; b ^= 1;
    }
}

// fused FC: bit-exact chain (fcb-first, slices ascending, fold .x+.y per slice)
__device__ __noinline__ void run_fc(const float* __restrict__ fcW,
                                    const float* __restrict__ fcb,
                                    float* __restrict__ out, int step,
                                    float (*AsB)[32][68], float (*WsB)[128][68],
                                    ull* sk) {
    const int tid = threadIdx.x, bid = blockIdx.x;
    const int bg = tid >> 4, cg = tid & 15;
    const int cbase = bid * 128;
    if (tid < 32) sk[tid] = 0ull;
    float rsum[4][8];
#pragma unroll
    for (int x = 0; x < 4; x++)
#pragma unroll
        for (int y = 0; y < 8; y++) rsum[x][y] = fcb[cbase + cg + 16 * y];

    issue_tile(g_h2, nullptr, Hsz, fcW, 0, cbase, AsB[0], WsB[0], tid);
    int b = 0;
    ull acc[4][8];
#pragma unroll
    for (int x = 0; x < 4; x++)
#pragma unroll
        for (int y = 0; y < 8; y++) acc[x][y] = 0ull;
    for (int u = 0; u < 16; u++) {
        if (u + 1 < 16) {
            issue_tile(g_h2, nullptr, Hsz, fcW, (u + 1) * 64, cbase,
                       AsB[b ^ 1], WsB[b ^ 1], tid);
            asm volatile("cp.async.wait_group 1;" ::: "memory");
        } else {
            asm volatile("cp.async.wait_group 0;" ::: "memory");
        }
        __syncthreads();
        compute64(AsB[b], WsB[b], acc, bg, cg);
        if (u & 1) {
#pragma unroll
            for (int x = 0; x < 4; x++)
#pragma unroll
                for (int y = 0; y < 8; y++) {
                    float2 p = up2(acc[x][y]);
                    rsum[x][y] += p.x + p.y;
                    acc[x][y] = 0ull;
                }
        }
        __syncthreads();
        b ^= 1;
    }
#pragma unroll
    for (int x = 0; x < 4; x++) {
        int row = bg + 8 * x;
        float* o = out + (size_t)row * ((size_t)Tsz * Vsz)
                 + (size_t)(step + 1) * Vsz + cbase;
        float bv = -3.4e38f; int bc = 0;
#pragma unroll
        for (int y = 0; y < 8; y++) {
            int c = cg + 16 * y;
            o[c] = rsum[x][y];
            if (rsum[x][y] > bv) { bv = rsum[x][y]; bc = cbase + c; }
        }
        atomicMax(&sk[row], packkey(bv, bc));
    }
    __syncthreads();
    if (tid < 32) atomicMax(&g_amax[tid], sk[tid]);
}

// ---------------- GRU gates + state update (frozen sum order) ----------------
__device__ __forceinline__ void gru_gates(const float* gi_pre, int nx,
                                          const float* bih, int nh,
                                          const float* phb, const float* bhh,
                                          float* h, float* ys, int nblk) {
    for (int idx = blockIdx.x * 128 + threadIdx.x; idx < Bsz * Hsz; idx += nblk * 128) {
        int b = idx >> 10, j = idx & 1023;
        float ir, iz, in_;
        if (gi_pre) {
            const float* g = gi_pre + (size_t)b * G3H;
            ir = g[j]; iz = g[Hsz + j]; in_ = g[2 * Hsz + j];
        } else {
            ir = bih[j]; iz = bih[Hsz + j]; in_ = bih[2 * Hsz + j];
            for (int s = 0; s < nx; s++) {
                const float* p = g_px + (size_t)s * Bsz * G3H + (size_t)b * G3H;
                ir += p[j]; iz += p[Hsz + j]; in_ += p[2 * Hsz + j];
            }
        }
        float hr = bhh[j], hz = bhh[Hsz + j], hn = bhh[2 * Hsz + j];
        for (int s = 0; s < nh; s++) {
            const float* p = phb + (size_t)s * Bsz * G3H + (size_t)b * G3H;
            hr += p[j]; hz += p[Hsz + j]; hn += p[2 * Hsz + j];
        }
        float r = 1.f / (1.f + expf(-(ir + hr)));
        float z = 1.f / (1.f + expf(-(iz + hz)));
        float n = tanhf(in_ + r * hn);
        float hv = h[idx];
        float hnew = (1.f - z) * n + z * hv;
        h[idx] = hnew;
        if (ys) ys[idx] = hnew;
    }
}

// ---------------- small kernels ----------------
__global__ void k_init(const int* __restrict__ trg) {
    int i = blockIdx.x * blockDim.x + threadIdx.x;
    if (i < Bsz * Hsz) { g_h1[i] = 0.f; g_h2[i] = 0.f; }
    if (i < Bsz) { g_tok[i] = trg[i * Tsz]; g_amax[i] = 0ull; }
}

__global__ void k_zero0(float* __restrict__ out) {
    int i = blockIdx.x * blockDim.x + threadIdx.x;
    if (i < Bsz * Vsz) {
        int b = i / Vsz, v = i - b * Vsz;
        out[(size_t)b * ((size_t)Tsz * Vsz) + v] = 0.f;
    }
}

// bulk input-gate GEMM
__global__ void __launch_bounds__(128, 3) k_big(
    const float* __restrict__ emb, const int* __restrict__ src,
    const float* __restrict__ W, const float* __restrict__ bias,
    int K, int gather)
{
    __shared__ float As[32][68];
    __shared__ float Ws[128][68];
    __shared__ int s_tok[32];
    int tid = threadIdx.x, tblk = blockIdx.y, cbase = blockIdx.x * 128;
    const float* A; int lda; const int* tp = nullptr;
    if (gather) {
        if (tid < 32) s_tok[tid] = src[tid * Ssz + tblk];
        __syncthreads();
        tp = s_tok; A = emb; lda = Esz;
    } else {
        A = g_ys0 + (size_t)tblk * Bsz * Hsz; lda = Hsz;
    }
    gemm_task(A, tp, lda, W, K, 0, K / 64, cbase,
              g_gi + (size_t)tblk * Bsz * G3H, G3H, bias, As, Ws);
}

// persistent encoder layer: W tile pinned in smem across all 128 steps.
__global__ void __launch_bounds__(128, 3) k_enc(
    const float* __restrict__ U, const float* __restrict__ bhh, int layer)
{
    __shared__ float As[32][68];
    __shared__ float Ws[128][68];
    const int tid = threadIdx.x, bid = blockIdx.x;
    const int bg = tid >> 4, cg = tid & 15;
    const bool active = bid < 384;
    const int ct = bid % 24, s = bid / 24;
    const int cbase = ct * 128, kb = s * 64;
    float* h = layer ? g_h2 : g_h1;
    if (active) {
#pragma unroll 4
        for (int r = 0; r < 16; r++) {
            int f4 = tid + r * 128, c = f4 >> 4, kq = f4 & 15;
            float4 v = *(const float4*)(U + (size_t)(cbase + c) * Hsz + kb + kq * 4);
            *(float4*)&Ws[c][kq * 4] = v;
        }
    }
    for (int t = 0; t < Ssz; t++) {
        if (active) {
            __syncthreads();
#pragma unroll
            for (int r = 0; r < 4; r++) {
                int f4 = tid + r * 128, row = f4 >> 4, kq = f4 & 15;
                float4 v = *(const float4*)(h + (size_t)row * Hsz + kb + kq * 4);
                *(float4*)&As[row][kq * 4] = v;
            }
            __syncthreads();
            ull acc[4][8];
#pragma unroll
            for (int i = 0; i < 4; i++)
#pragma unroll
                for (int j = 0; j < 8; j++) acc[i][j] = 0ull;
            compute64(As, Ws, acc, bg, cg);
            float* outp = g_ph + (size_t)s * Bsz * G3H;
#pragma unroll
            for (int i = 0; i < 4; i++) {
                float* o = outp + (size_t)(bg + 8 * i) * G3H + cbase;
#pragma unroll
                for (int j = 0; j < 8; j++) {
                    float2 p = up2(acc[i][j]);
                    o[cg + 16 * j] = p.x + p.y;
                }
            }
        }
        gbar();
        gru_gates(g_gi + (size_t)t * Bsz * G3H, 0, nullptr, 16, g_ph, bhh,
                  h, layer ? nullptr : (g_ys0 + (size_t)t * Bsz * Hsz), NBLK_ENC);
        gbar();
    }
}

// persistent decoder: gh GEMMs for step t+1 overlapped with FC of step t
__global__ void __launch_bounds__(128, 2) k_dec(
    const float* __restrict__ demb,
    const float* __restrict__ dW0, const float* __restrict__ dU0,
    const float* __restrict__ dbi0, const float* __restrict__ dbh0,
    const float* __restrict__ dW1, const float* __restrict__ dU1,
    const float* __restrict__ dbi1, const float* __restrict__ dbh1,
    const float* __restrict__ fcW, const float* __restrict__ fcb,
    float* __restrict__ out)
{
    extern __shared__ float dyn[];
    float (*AsB)[32][68] = (float(*)[32][68])dyn;
    float (*WsB)[128][68] = (float(*)[128][68])(dyn + 2 * 32 * 68);
    __shared__ int s_tok[32];
    __shared__ ull sk[32];
    int tid = threadIdx.x, bid = blockIdx.x;
    DecCtx ctx = {demb, dW0, dU0, dW1, dU1, s_tok};

    for (int step = 0; step < Tsz - 1; step++) {
        if (tid < 32)
            s_tok[tid] = (step == 0)
                ? g_tok[tid]
                : (int)(0xFFFFFFFFu - (unsigned)(g_amax[tid] & 0xFFFFFFFFull));
        __syncthreads();
        // P1: gi (192 tasks); at step 0 also ghL0+ghL1 (960 total)
        run_tasks(0, bid, (step == 0) ? 960 : 192, NBLK_DEC, ctx, AsB, WsB);
        gbar();
        // P2: gates -> h1 ; reset argmax accumulator
        gru_gates(nullptr, 8, dbi0, 16, g_ph, dbh0, g_h1, nullptr, NBLK_DEC);
        if (bid == 0 && tid < 32) g_amax[tid] = 0ull;
        gbar();
        // P3: gi2 (384 tasks)
        run_tasks(1, bid, 384, NBLK_DEC, ctx, AsB, WsB);
        gbar();
        // P4: gates -> h2 (reads g_ph1)
        gru_gates(nullptr, 16, dbi1, 16, g_ph1, dbh1, g_h2, nullptr, NBLK_DEC);
        gbar();
        // P5: blocks 0-249 FC+argmax; blocks 250-295 next step's ghL0/ghL1
        if (bid < 250)
            run_fc(fcW, fcb, out, step, AsB, WsB, sk);
        else
            run_tasks(0, 192 + (bid - 250), 960, 46, ctx, AsB, WsB);
        gbar();
    }
}

extern "C" void kernel_launch(void* const* d_in, const int* in_sizes, int n_in,
                              void* d_out, int out_size) {
    const int* src = (const int*)d_in[0];
    const int* trg = (const int*)d_in[1];
    const float* enc_emb = (const float*)d_in[3];
    const float* eW0 = (const float*)d_in[4];
    const float* eU0 = (const float*)d_in[5];
    const float* ebi0 = (const float*)d_in[6];
    const float* ebh0 = (const float*)d_in[7];
    const float* eW1 = (const float*)d_in[8];
    const float* eU1 = (const float*)d_in[9];
    const float* ebi1 = (const float*)d_in[10];
    const float* ebh1 = (const float*)d_in[11];
    const float* demb = (const float*)d_in[12];
    const float* dW0 = (const float*)d_in[13];
    const float* dU0 = (const float*)d_in[14];
    const float* dbi0 = (const float*)d_in[15];
    const float* dbh0 = (const float*)d_in[16];
    const float* dW1 = (const float*)d_in[17];
    const float* dU1 = (const float*)d_in[18];
    const float* dbi1 = (const float*)d_in[19];
    const float* dbh1 = (const float*)d_in[20];
    const float* fcW = (const float*)d_in[21];
    const float* fcb = (const float*)d_in[22];
    float* out = (float*)d_out;

    const int DYN = (2 * 32 * 68 + 2 * 128 * 68) * 4;   // 87040 B
    cudaFuncSetAttribute(k_dec, cudaFuncAttributeMaxDynamicSharedMemorySize, DYN);

    k_init<<<128, 256>>>(trg);
    k_zero0<<<(Bsz * Vsz + 255) / 256, 256>>>(out);

    k_big<<<dim3(24, 128), 128>>>(enc_emb, src, eW0, ebi0, Esz, 1);
    k_enc<<<NBLK_ENC, 128>>>(eU0, ebh0, 0);
    k_big<<<dim3(24, 128), 128>>>(nullptr, nullptr, eW1, ebi1, Hsz, 0);
    k_enc<<<NBLK_ENC, 128>>>(eU1, ebh1, 1);
    k_dec<<<NBLK_DEC, 128, DYN>>>(demb, dW0, dU0, dbi0, dbh0,
                                  dW1, dU1, dbi1, dbh1, fcW, fcb, out);
}